// round 11
// baseline (speedup 1.0000x reference)
#include <cuda_runtime.h>
#include <math.h>

#define CC 256
#define HW 65536
#define NSWMAX 12
#define ROTTHR 1e-8f   // relative off-diag threshold^2 (rel 1e-4)

// ---- scratch (static device arrays; no allocation anywhere) ----
__device__ float g_B[CC * HW];   // 64MB: per-channel working matrix, column-major
__device__ float g_T[CC * HW];   // 64MB: T = diag(f) * B^T A
__device__ float g_R[CC * HW];   // 64MB: recon = B * T
__device__ float g_mean[CC];
__device__ float g_max[CC];
__device__ int   g_k[CC];
__device__ float g_fact[CC * CC];
__device__ float g_cat[2 * HW];

__device__ __forceinline__ float warp_sum(float a) {
#pragma unroll
    for (int o = 16; o > 0; o >>= 1) a += __shfl_xor_sync(0xFFFFFFFFu, a, o);
    return a;
}

// ---------------- stage 0: per-channel mean & max over HxW ----------------
__global__ void k_stats(const float* __restrict__ x) {
    int c = blockIdx.x, t = threadIdx.x;
    const float* xc = x + (size_t)c * HW;
    double s = 0.0;
    float m = -3.4e38f;
    for (int i = t; i < HW; i += 256) {
        float v = xc[i];
        s += (double)v;
        m = fmaxf(m, v);
    }
    __shared__ double ss[256];
    __shared__ float  sm[256];
    ss[t] = s; sm[t] = m;
    __syncthreads();
    for (int o = 128; o > 0; o >>= 1) {
        if (t < o) { ss[t] += ss[t + o]; sm[t] = fmaxf(sm[t], sm[t + o]); }
        __syncthreads();
    }
    if (t == 0) {
        g_mean[c] = (float)(ss[0] / (double)HW);
        g_max[c]  = sm[0];
    }
}

// ---------------- stage 1: channel attention -> k[c] ----------------
__global__ void k_att(const float* __restrict__ w1, const float* __restrict__ w2,
                      const int* __restrict__ kvp) {
    int t = threadIdx.x;
    __shared__ float  mu[256], mx[256];
    __shared__ double hA[16], hM[16];
    __shared__ double sy[256];
    __shared__ double ymin, ymax;
    mu[t] = g_mean[t]; mx[t] = g_max[t];
    __syncthreads();
    if (t < 16) {
        double a = 0.0, b = 0.0;
        for (int c2 = 0; c2 < 256; c2++) {
            double w = (double)w1[t * 256 + c2];
            a += w * (double)mu[c2];
            b += w * (double)mx[c2];
        }
        hA[t] = a > 0.0 ? a : 0.0;   // relu
        hM[t] = b > 0.0 ? b : 0.0;
    }
    __syncthreads();
    {
        double acc = 0.0;
        for (int r = 0; r < 16; r++)
            acc += (double)w2[t * 16 + r] * (hA[r] + hM[r]);
        sy[t] = 1.0 / (1.0 + exp(-acc));     // sigmoid(y_avg + y_max)
    }
    __syncthreads();
    if (t == 0) {
        double mn = sy[0], mv = sy[0];
        for (int i = 1; i < 256; i++) { mn = fmin(mn, sy[i]); mv = fmax(mv, sy[i]); }
        ymin = mn; ymax = mv;
    }
    __syncthreads();
    // kv hedge: accept int32 or float32 bit patterns
    int iv = *kvp;
    float fv = __int_as_float(iv);
    double kvd = (iv >= 0 && iv <= 1000000) ? (double)iv : (double)fv;
    double yc = (sy[t] - ymin) / (ymax - ymin + 1e-20);
    int k = (int)floor(256.0 * kvd * yc);
    if (k < 0) k = 0;
    if (k > 256) k = 256;
    g_k[t] = k;
}

// ---------------- stage 2: transpose x -> column-major B ----------------
__global__ void k_tr(const float* __restrict__ x) {
    __shared__ float tile[32][33];
    int c = blockIdx.z;
    int i0 = blockIdx.y * 32, j0 = blockIdx.x * 32;
    int tx = threadIdx.x, ty = threadIdx.y;
    const float* xc = x + (size_t)c * HW;
    float* bc = g_B + (size_t)c * HW;
#pragma unroll
    for (int m = 0; m < 4; m++)
        tile[ty + 8 * m][tx] = xc[(i0 + ty + 8 * m) * 256 + j0 + tx];
    __syncthreads();
#pragma unroll
    for (int m = 0; m < 4; m++)
        bc[(j0 + ty + 8 * m) * 256 + i0 + tx] = tile[tx][ty + 8 * m];
}

// ---------------- stage 3: blocked one-sided Jacobi (Hestenes), no V ----------------
// 256 threads (8 warps), 3 CTAs/SM. 8 blocks of 32 columns.
// Intra-block: 31 tournament rounds x 16 pairs (2 pairs/warp, ILP2), smem + cached norms.
// Cross-block: each warp holds 4 register columns (w+8j); round r rotates reg-col i
// against smem col (i+r)&31 (bijection -> 32 disjoint rotations, ILP4 dot chains).
__global__ void __launch_bounds__(256, 3) k_jacobi() {
    int c = blockIdx.x;
    float* Bg = g_B + (size_t)c * HW;
    int t = threadIdx.x, lane = t & 31, w = t >> 5;   // w in 0..7

    __shared__ float sj[8192];     // 32KB: one 32-column block
    __shared__ float snj[32];      // column norms^2 of smem block
    __shared__ int s_flag;

    for (int sweep = 0; sweep < NSWMAX; sweep++) {
        if (t == 0) s_flag = 0;
        __syncthreads();
        for (int bi = 0; bi < 8; bi++) {
            // ---- load block bi: warp w loads cols w+8h + computes norms (4 chains)
            {
                float nrm[4];
#pragma unroll
                for (int h = 0; h < 4; h++) {
                    int col = w + 8 * h;
                    const float4* src = (const float4*)(Bg + (bi * 32 + col) * 256);
                    float4* dst = (float4*)(sj + col * 256);
                    float4 v0 = src[lane * 2], v1 = src[lane * 2 + 1];
                    dst[lane * 2] = v0; dst[lane * 2 + 1] = v1;
                    nrm[h] = v0.x*v0.x + v0.y*v0.y + v0.z*v0.z + v0.w*v0.w
                           + v1.x*v1.x + v1.y*v1.y + v1.z*v1.z + v1.w*v1.w;
                }
#pragma unroll
                for (int o = 16; o > 0; o >>= 1) {
                    nrm[0] += __shfl_xor_sync(0xFFFFFFFFu, nrm[0], o);
                    nrm[1] += __shfl_xor_sync(0xFFFFFFFFu, nrm[1], o);
                    nrm[2] += __shfl_xor_sync(0xFFFFFFFFu, nrm[2], o);
                    nrm[3] += __shfl_xor_sync(0xFFFFFFFFu, nrm[3], o);
                }
                if (lane == 0) {
#pragma unroll
                    for (int h = 0; h < 4; h++) snj[w + 8 * h] = nrm[h];
                }
            }
            __syncthreads();
            // ---- intra-block tournament: 31 rounds x 16 pairs (2 per warp)
            for (int r = 0; r < 31; r++) {
                int pA, qA, pB, qB;
                {
                    int s0 = w;
                    pA = (s0 == 0) ? 0 : 1 + (s0 - 1 + r) % 31;
                    qA = 1 + (30 - s0 + r) % 31;
                    int s1 = w + 8;
                    pB = 1 + (s1 - 1 + r) % 31;
                    qB = 1 + (30 - s1 + r) % 31;
                }
                float4* cpA = (float4*)(sj + pA * 256);
                float4* cqA = (float4*)(sj + qA * 256);
                float4* cpB = (float4*)(sj + pB * 256);
                float4* cqB = (float4*)(sj + qB * 256);
                float4 pA0 = cpA[lane * 2], pA1 = cpA[lane * 2 + 1];
                float4 qA0 = cqA[lane * 2], qA1 = cqA[lane * 2 + 1];
                float4 pB0 = cpB[lane * 2], pB1 = cpB[lane * 2 + 1];
                float4 qB0 = cqB[lane * 2], qB1 = cqB[lane * 2 + 1];
                float dA, dB;
                {
                    float a = pA0.x * qA0.x;
                    a = fmaf(pA0.y, qA0.y, a); a = fmaf(pA0.z, qA0.z, a);
                    a = fmaf(pA0.w, qA0.w, a); a = fmaf(pA1.x, qA1.x, a);
                    a = fmaf(pA1.y, qA1.y, a); a = fmaf(pA1.z, qA1.z, a);
                    a = fmaf(pA1.w, qA1.w, a);
                    float b = pB0.x * qB0.x;
                    b = fmaf(pB0.y, qB0.y, b); b = fmaf(pB0.z, qB0.z, b);
                    b = fmaf(pB0.w, qB0.w, b); b = fmaf(pB1.x, qB1.x, b);
                    b = fmaf(pB1.y, qB1.y, b); b = fmaf(pB1.z, qB1.z, b);
                    b = fmaf(pB1.w, qB1.w, b);
#pragma unroll
                    for (int o = 16; o > 0; o >>= 1) {
                        a += __shfl_xor_sync(0xFFFFFFFFu, a, o);
                        b += __shfl_xor_sync(0xFFFFFFFFu, b, o);
                    }
                    dA = a; dB = b;
                }
                float appA = snj[pA], aqqA = snj[qA];
                float appB = snj[pB], aqqB = snj[qB];
                if (dA * dA > ROTTHR * appA * aqqA) {
                    float tau = (aqqA - appA) / (2.0f * dA);
                    float tt  = copysignf(1.0f, tau) / (fabsf(tau) + sqrtf(1.0f + tau * tau));
                    float cth = 1.0f / sqrtf(1.0f + tt * tt);
                    float sth = tt * cth;
                    float4 np, nq;
                    np.x = cth*pA0.x - sth*qA0.x;  nq.x = sth*pA0.x + cth*qA0.x;
                    np.y = cth*pA0.y - sth*qA0.y;  nq.y = sth*pA0.y + cth*qA0.y;
                    np.z = cth*pA0.z - sth*qA0.z;  nq.z = sth*pA0.z + cth*qA0.z;
                    np.w = cth*pA0.w - sth*qA0.w;  nq.w = sth*pA0.w + cth*qA0.w;
                    cpA[lane * 2] = np;  cqA[lane * 2] = nq;
                    np.x = cth*pA1.x - sth*qA1.x;  nq.x = sth*pA1.x + cth*qA1.x;
                    np.y = cth*pA1.y - sth*qA1.y;  nq.y = sth*pA1.y + cth*qA1.y;
                    np.z = cth*pA1.z - sth*qA1.z;  nq.z = sth*pA1.z + cth*qA1.z;
                    np.w = cth*pA1.w - sth*qA1.w;  nq.w = sth*pA1.w + cth*qA1.w;
                    cpA[lane * 2 + 1] = np;  cqA[lane * 2 + 1] = nq;
                    if (lane == 0) {
                        snj[pA] = appA - tt * dA;
                        snj[qA] = aqqA + tt * dA;
                        s_flag = 1;
                    }
                }
                if (dB * dB > ROTTHR * appB * aqqB) {
                    float tau = (aqqB - appB) / (2.0f * dB);
                    float tt  = copysignf(1.0f, tau) / (fabsf(tau) + sqrtf(1.0f + tau * tau));
                    float cth = 1.0f / sqrtf(1.0f + tt * tt);
                    float sth = tt * cth;
                    float4 np, nq;
                    np.x = cth*pB0.x - sth*qB0.x;  nq.x = sth*pB0.x + cth*qB0.x;
                    np.y = cth*pB0.y - sth*qB0.y;  nq.y = sth*pB0.y + cth*qB0.y;
                    np.z = cth*pB0.z - sth*qB0.z;  nq.z = sth*pB0.z + cth*qB0.z;
                    np.w = cth*pB0.w - sth*qB0.w;  nq.w = sth*pB0.w + cth*qB0.w;
                    cpB[lane * 2] = np;  cqB[lane * 2] = nq;
                    np.x = cth*pB1.x - sth*qB1.x;  nq.x = sth*pB1.x + cth*qB1.x;
                    np.y = cth*pB1.y - sth*qB1.y;  nq.y = sth*pB1.y + cth*qB1.y;
                    np.z = cth*pB1.z - sth*qB1.z;  nq.z = sth*pB1.z + cth*qB1.z;
                    np.w = cth*pB1.w - sth*qB1.w;  nq.w = sth*pB1.w + cth*qB1.w;
                    cpB[lane * 2 + 1] = np;  cqB[lane * 2 + 1] = nq;
                    if (lane == 0) {
                        snj[pB] = appB - tt * dB;
                        snj[qB] = aqqB + tt * dB;
                        s_flag = 1;
                    }
                }
                __syncthreads();
            }
            // ---- move cols w+8h of bi into registers (exact norms, 4 chains)
            float rp[4][8], app[4];
            {
                float nrm[4];
#pragma unroll
                for (int h = 0; h < 4; h++) {
                    const float4* c0 = (const float4*)(sj + (w + 8 * h) * 256);
                    float4 a0 = c0[lane * 2], a1 = c0[lane * 2 + 1];
                    rp[h][0]=a0.x; rp[h][1]=a0.y; rp[h][2]=a0.z; rp[h][3]=a0.w;
                    rp[h][4]=a1.x; rp[h][5]=a1.y; rp[h][6]=a1.z; rp[h][7]=a1.w;
                    float a = 0.f;
#pragma unroll
                    for (int m = 0; m < 8; m++) a = fmaf(rp[h][m], rp[h][m], a);
                    nrm[h] = a;
                }
#pragma unroll
                for (int o = 16; o > 0; o >>= 1) {
                    nrm[0] += __shfl_xor_sync(0xFFFFFFFFu, nrm[0], o);
                    nrm[1] += __shfl_xor_sync(0xFFFFFFFFu, nrm[1], o);
                    nrm[2] += __shfl_xor_sync(0xFFFFFFFFu, nrm[2], o);
                    nrm[3] += __shfl_xor_sync(0xFFFFFFFFu, nrm[3], o);
                }
#pragma unroll
                for (int h = 0; h < 4; h++) app[h] = nrm[h];
            }
            // ---- cross-block phase
            for (int bj = bi + 1; bj < 8; bj++) {
                // load bj (own cols; same-warp ordering vs. prior reads) + norms
                {
                    float nrm[4];
#pragma unroll
                    for (int h = 0; h < 4; h++) {
                        int col = w + 8 * h;
                        const float4* src = (const float4*)(Bg + (bj * 32 + col) * 256);
                        float4* dst = (float4*)(sj + col * 256);
                        float4 v0 = src[lane * 2], v1 = src[lane * 2 + 1];
                        dst[lane * 2] = v0; dst[lane * 2 + 1] = v1;
                        nrm[h] = v0.x*v0.x + v0.y*v0.y + v0.z*v0.z + v0.w*v0.w
                               + v1.x*v1.x + v1.y*v1.y + v1.z*v1.z + v1.w*v1.w;
                    }
#pragma unroll
                    for (int o = 16; o > 0; o >>= 1) {
                        nrm[0] += __shfl_xor_sync(0xFFFFFFFFu, nrm[0], o);
                        nrm[1] += __shfl_xor_sync(0xFFFFFFFFu, nrm[1], o);
                        nrm[2] += __shfl_xor_sync(0xFFFFFFFFu, nrm[2], o);
                        nrm[3] += __shfl_xor_sync(0xFFFFFFFFu, nrm[3], o);
                    }
                    if (lane == 0) {
#pragma unroll
                        for (int h = 0; h < 4; h++) snj[w + 8 * h] = nrm[h];
                    }
                }
                __syncthreads();
                for (int r = 0; r < 32; r++) {
                    int qi[4];
                    float bq[4][8];
                    float d[4];
#pragma unroll
                    for (int j = 0; j < 4; j++) {
                        qi[j] = ((w + 8 * j) + r) & 31;
                        const float4* cq = (const float4*)(sj + qi[j] * 256);
                        float4 x0 = cq[lane * 2], x1 = cq[lane * 2 + 1];
                        bq[j][0]=x0.x; bq[j][1]=x0.y; bq[j][2]=x0.z; bq[j][3]=x0.w;
                        bq[j][4]=x1.x; bq[j][5]=x1.y; bq[j][6]=x1.z; bq[j][7]=x1.w;
                        float a = 0.f;
#pragma unroll
                        for (int m = 0; m < 8; m++) a = fmaf(rp[j][m], bq[j][m], a);
                        d[j] = a;
                    }
#pragma unroll
                    for (int o = 16; o > 0; o >>= 1) {   // 4 interleaved chains
                        d[0] += __shfl_xor_sync(0xFFFFFFFFu, d[0], o);
                        d[1] += __shfl_xor_sync(0xFFFFFFFFu, d[1], o);
                        d[2] += __shfl_xor_sync(0xFFFFFFFFu, d[2], o);
                        d[3] += __shfl_xor_sync(0xFFFFFFFFu, d[3], o);
                    }
#pragma unroll
                    for (int j = 0; j < 4; j++) {
                        float aqq = snj[qi[j]];
                        float dj = d[j];
                        if (dj * dj > ROTTHR * app[j] * aqq) {
                            float tau = (aqq - app[j]) / (2.0f * dj);
                            float tt  = copysignf(1.0f, tau) / (fabsf(tau) + sqrtf(1.0f + tau * tau));
                            float cth = 1.0f / sqrtf(1.0f + tt * tt);
                            float sth = tt * cth;
                            float4* cq = (float4*)(sj + qi[j] * 256);
                            float4 nv;
                            nv.x = fmaf(sth, rp[j][0], cth * bq[j][0]);
                            nv.y = fmaf(sth, rp[j][1], cth * bq[j][1]);
                            nv.z = fmaf(sth, rp[j][2], cth * bq[j][2]);
                            nv.w = fmaf(sth, rp[j][3], cth * bq[j][3]);
                            cq[lane * 2] = nv;
                            nv.x = fmaf(sth, rp[j][4], cth * bq[j][4]);
                            nv.y = fmaf(sth, rp[j][5], cth * bq[j][5]);
                            nv.z = fmaf(sth, rp[j][6], cth * bq[j][6]);
                            nv.w = fmaf(sth, rp[j][7], cth * bq[j][7]);
                            cq[lane * 2 + 1] = nv;
#pragma unroll
                            for (int m = 0; m < 8; m++)
                                rp[j][m] = fmaf(cth, rp[j][m], -sth * bq[j][m]);
                            app[j] = app[j] - tt * dj;
                            if (lane == 0) { snj[qi[j]] = aqq + tt * dj; s_flag = 1; }
                        }
                    }
                    __syncthreads();
                }
                // store bj back (own cols; round loop ended with barrier)
#pragma unroll
                for (int h = 0; h < 4; h++) {
                    int col = w + 8 * h;
                    float4* dst = (float4*)(Bg + (bj * 32 + col) * 256);
                    const float4* src = (const float4*)(sj + col * 256);
                    dst[lane * 2] = src[lane * 2];
                    dst[lane * 2 + 1] = src[lane * 2 + 1];
                }
            }
            // ---- store register columns back (own cols)
#pragma unroll
            for (int h = 0; h < 4; h++) {
                float4* dst = (float4*)(Bg + (bi * 32 + w + 8 * h) * 256);
                dst[lane * 2]     = make_float4(rp[h][0], rp[h][1], rp[h][2], rp[h][3]);
                dst[lane * 2 + 1] = make_float4(rp[h][4], rp[h][5], rp[h][6], rp[h][7]);
            }
            __syncthreads();
        }
        __syncthreads();
        int done = (s_flag == 0);
        __syncthreads();
        if (done) break;
    }
}

// ---------------- stage 4: column norms, rank, keep factor ----------------
__global__ void k_fact() {
    int c = blockIdx.x, t = threadIdx.x, lane = t & 31, w = t >> 5;
    __shared__ float s2[256];
    const float* B = g_B + (size_t)c * HW;
    for (int j = w; j < 256; j += 8) {
        const float* col = B + j * 256;
        float a = 0.f;
#pragma unroll
        for (int m = 0; m < 8; m++) {
            float v = col[lane + 32 * m];
            a = fmaf(v, v, a);
        }
        a = warp_sum(a);
        if (lane == 0) s2[j] = a;
    }
    __syncthreads();
    float mys = s2[t];
    int kc = g_k[c];
    int rank = 0;
    for (int j = 0; j < 256; j++) {
        float v = s2[j];
        rank += (v > mys) || (v == mys && j < t);
    }
    g_fact[c * 256 + t] = (rank < kc) ? 1.0f / fmaxf(mys, 1e-20f) : 0.0f;
}

// ---------------- stage 5: T = diag(f) * B^T A  (C = M*N, M row-major = B^T) ----------
__global__ void __launch_bounds__(256) k_gemmT(const float* __restrict__ x) {
    int c = blockIdx.z;
    const float* M = g_B + (size_t)c * HW;   // M[j][i] = B(i,j)
    const float* N = x + (size_t)c * HW;     // A row-major
    float* C = g_T + (size_t)c * HW;
    int m0 = blockIdx.y * 64, n0 = blockIdx.x * 64;
    __shared__ float Ms[16][68], Ns[16][68];
    int t = threadIdx.x;
    int tx = t & 15, ty = t >> 4;
    float acc[4][4] = {};
    for (int k0 = 0; k0 < 256; k0 += 16) {
#pragma unroll
        for (int u = 0; u < 4; u++) {
            int id = t + 256 * u;
            int kk = id & 15, mm = id >> 4;
            Ms[kk][mm] = M[(m0 + mm) * 256 + k0 + kk];
        }
#pragma unroll
        for (int u = 0; u < 4; u++) {
            int id = t + 256 * u;
            int kk = id >> 6, nn = id & 63;
            Ns[kk][nn] = N[(k0 + kk) * 256 + n0 + nn];
        }
        __syncthreads();
#pragma unroll
        for (int kk = 0; kk < 16; kk++) {
            float a[4], b[4];
#pragma unroll
            for (int i = 0; i < 4; i++) a[i] = Ms[kk][ty * 4 + i];
#pragma unroll
            for (int j = 0; j < 4; j++) b[j] = Ns[kk][tx * 4 + j];
#pragma unroll
            for (int i = 0; i < 4; i++)
#pragma unroll
                for (int j = 0; j < 4; j++) acc[i][j] = fmaf(a[i], b[j], acc[i][j]);
        }
        __syncthreads();
    }
    const float* f = g_fact + c * 256;
#pragma unroll
    for (int i = 0; i < 4; i++) {
        float fi = f[m0 + ty * 4 + i];
#pragma unroll
        for (int j = 0; j < 4; j++)
            C[(m0 + ty * 4 + i) * 256 + n0 + tx * 4 + j] = acc[i][j] * fi;
    }
}

// ---------------- stage 6: R = B * T  (= M^T * N with M as above) ----------------
__global__ void __launch_bounds__(256) k_gemmR() {
    int c = blockIdx.z;
    const float* M = g_B + (size_t)c * HW;   // M[j][i] = B(i,j); need M^T * T
    const float* N = g_T + (size_t)c * HW;
    float* C = g_R + (size_t)c * HW;
    int m0 = blockIdx.y * 64, n0 = blockIdx.x * 64;
    __shared__ float Ms[16][68], Ns[16][68];
    int t = threadIdx.x;
    int tx = t & 15, ty = t >> 4;
    float acc[4][4] = {};
    for (int k0 = 0; k0 < 256; k0 += 16) {
#pragma unroll
        for (int u = 0; u < 4; u++) {
            int id = t + 256 * u;
            int kk = id >> 6, mm = id & 63;
            Ms[kk][mm] = M[(k0 + kk) * 256 + m0 + mm];   // M^T tile, coalesced
        }
#pragma unroll
        for (int u = 0; u < 4; u++) {
            int id = t + 256 * u;
            int kk = id >> 6, nn = id & 63;
            Ns[kk][nn] = N[(k0 + kk) * 256 + n0 + nn];
        }
        __syncthreads();
#pragma unroll
        for (int kk = 0; kk < 16; kk++) {
            float a[4], b[4];
#pragma unroll
            for (int i = 0; i < 4; i++) a[i] = Ms[kk][ty * 4 + i];
#pragma unroll
            for (int j = 0; j < 4; j++) b[j] = Ns[kk][tx * 4 + j];
#pragma unroll
            for (int i = 0; i < 4; i++)
#pragma unroll
                for (int j = 0; j < 4; j++) acc[i][j] = fmaf(a[i], b[j], acc[i][j]);
        }
        __syncthreads();
    }
#pragma unroll
    for (int i = 0; i < 4; i++)
#pragma unroll
        for (int j = 0; j < 4; j++)
            C[(m0 + ty * 4 + i) * 256 + n0 + tx * 4 + j] = acc[i][j];
}

// ---------------- stage 7: channel mean & max of recon ----------------
__global__ void k_avgmax() {
    int pix = blockIdx.x * 1024 + threadIdx.x;
    float s = 0.f, m = -3.4e38f;
    for (int c = 0; c < 256; c++) {
        float v = g_R[(size_t)c * HW + pix];
        s += v;
        m = fmaxf(m, v);
    }
    g_cat[pix]      = s * (1.0f / 256.0f);
    g_cat[HW + pix] = m;
}

// ---------------- stage 8: 7x7 conv (pad 3) + EPS clamp + sigmoid ----------------
__global__ void k_conv(const float* __restrict__ cw, float* __restrict__ out) {
    __shared__ float wsm[98];
    int tx = threadIdx.x, ty = threadIdx.y;
    int tid = ty * 32 + tx;
    if (tid < 98) wsm[tid] = cw[tid];
    __syncthreads();
    int gx = blockIdx.x * 32 + tx;
    int gy = blockIdx.y * 8 + ty;
    float acc = 0.f;
#pragma unroll
    for (int ci = 0; ci < 2; ci++) {
#pragma unroll
        for (int kh = 0; kh < 7; kh++) {
            int iy = gy + kh - 3;
            if (iy < 0 || iy > 255) continue;
#pragma unroll
            for (int kw = 0; kw < 7; kw++) {
                int ix = gx + kw - 3;
                if (ix < 0 || ix > 255) continue;
                acc = fmaf(g_cat[ci * HW + iy * 256 + ix], wsm[ci * 49 + kh * 7 + kw], acc);
            }
        }
    }
    const float EPSF = 2.220446049250313e-16f;
    if (acc < EPSF) acc = EPSF;
    out[gy * 256 + gx] = 1.0f / (1.0f + expf(-acc));
}

// ---------------- launch ----------------
extern "C" void kernel_launch(void* const* d_in, const int* in_sizes, int n_in,
                              void* d_out, int out_size) {
    const float* x  = (const float*)d_in[0];
    const float* w1 = (const float*)d_in[1];
    const float* w2 = (const float*)d_in[2];
    const float* cw = (const float*)d_in[3];
    const int*   kv = (const int*)d_in[4];

    k_stats<<<256, 256>>>(x);
    k_att<<<1, 256>>>(w1, w2, kv);
    k_tr<<<dim3(8, 8, 256), dim3(32, 8)>>>(x);
    k_jacobi<<<256, 256>>>();
    k_fact<<<256, 256>>>();
    k_gemmT<<<dim3(4, 4, 256), 256>>>(x);
    k_gemmR<<<dim3(4, 4, 256), 256>>>();
    k_avgmax<<<64, 1024>>>();
    k_conv<<<dim3(8, 32), dim3(32, 8)>>>(cw, (float*)d_out);
}

// round 12
// speedup vs baseline: 1.3977x; 1.3977x over previous
#include <cuda_runtime.h>
#include <math.h>

#define CC 256
#define HW 65536
#define NSWMAX 10
#define ROTTHR 1e-8f   // relative off-diag threshold^2 (rel 1e-4)

// ---- scratch (static device arrays; no allocation anywhere) ----
__device__ float g_B[CC * HW];   // 64MB: per-channel working matrix, column-major
__device__ float g_T[CC * HW];   // 64MB: T = diag(f) * B^T A
__device__ float g_R[CC * HW];   // 64MB: recon = B * T
__device__ float g_mean[CC];
__device__ float g_max[CC];
__device__ int   g_k[CC];
__device__ float g_fact[CC * CC];
__device__ float g_cat[2 * HW];

__device__ __forceinline__ float warp_sum(float a) {
#pragma unroll
    for (int o = 16; o > 0; o >>= 1) a += __shfl_xor_sync(0xFFFFFFFFu, a, o);
    return a;
}

// ---------------- stage 0: per-channel mean & max over HxW ----------------
__global__ void k_stats(const float* __restrict__ x) {
    int c = blockIdx.x, t = threadIdx.x;
    const float* xc = x + (size_t)c * HW;
    double s = 0.0;
    float m = -3.4e38f;
    for (int i = t; i < HW; i += 256) {
        float v = xc[i];
        s += (double)v;
        m = fmaxf(m, v);
    }
    __shared__ double ss[256];
    __shared__ float  sm[256];
    ss[t] = s; sm[t] = m;
    __syncthreads();
    for (int o = 128; o > 0; o >>= 1) {
        if (t < o) { ss[t] += ss[t + o]; sm[t] = fmaxf(sm[t], sm[t + o]); }
        __syncthreads();
    }
    if (t == 0) {
        g_mean[c] = (float)(ss[0] / (double)HW);
        g_max[c]  = sm[0];
    }
}

// ---------------- stage 1: channel attention -> k[c] ----------------
__global__ void k_att(const float* __restrict__ w1, const float* __restrict__ w2,
                      const int* __restrict__ kvp) {
    int t = threadIdx.x;
    __shared__ float  mu[256], mx[256];
    __shared__ double hA[16], hM[16];
    __shared__ double sy[256];
    __shared__ double ymin, ymax;
    mu[t] = g_mean[t]; mx[t] = g_max[t];
    __syncthreads();
    if (t < 16) {
        double a = 0.0, b = 0.0;
        for (int c2 = 0; c2 < 256; c2++) {
            double w = (double)w1[t * 256 + c2];
            a += w * (double)mu[c2];
            b += w * (double)mx[c2];
        }
        hA[t] = a > 0.0 ? a : 0.0;   // relu
        hM[t] = b > 0.0 ? b : 0.0;
    }
    __syncthreads();
    {
        double acc = 0.0;
        for (int r = 0; r < 16; r++)
            acc += (double)w2[t * 16 + r] * (hA[r] + hM[r]);
        sy[t] = 1.0 / (1.0 + exp(-acc));     // sigmoid(y_avg + y_max)
    }
    __syncthreads();
    if (t == 0) {
        double mn = sy[0], mv = sy[0];
        for (int i = 1; i < 256; i++) { mn = fmin(mn, sy[i]); mv = fmax(mv, sy[i]); }
        ymin = mn; ymax = mv;
    }
    __syncthreads();
    // kv hedge: accept int32 or float32 bit patterns
    int iv = *kvp;
    float fv = __int_as_float(iv);
    double kvd = (iv >= 0 && iv <= 1000000) ? (double)iv : (double)fv;
    double yc = (sy[t] - ymin) / (ymax - ymin + 1e-20);
    int k = (int)floor(256.0 * kvd * yc);
    if (k < 0) k = 0;
    if (k > 256) k = 256;
    g_k[t] = k;
}

// ---------------- stage 2: transpose x -> column-major B ----------------
__global__ void k_tr(const float* __restrict__ x) {
    __shared__ float tile[32][33];
    int c = blockIdx.z;
    int i0 = blockIdx.y * 32, j0 = blockIdx.x * 32;
    int tx = threadIdx.x, ty = threadIdx.y;
    const float* xc = x + (size_t)c * HW;
    float* bc = g_B + (size_t)c * HW;
#pragma unroll
    for (int m = 0; m < 4; m++)
        tile[ty + 8 * m][tx] = xc[(i0 + ty + 8 * m) * 256 + j0 + tx];
    __syncthreads();
#pragma unroll
    for (int m = 0; m < 4; m++)
        bc[(j0 + ty + 8 * m) * 256 + i0 + tx] = tile[tx][ty + 8 * m];
}

// ---------------- stage 3: blocked one-sided Jacobi (Hestenes), no V ----------------
// 512 threads (16 warps), 2 CTAs/SM. 8 blocks of 32 columns.
// Intra-block: 31 tournament rounds x 16 warp-pairs in smem, cached norms.
// Cross-block: each warp holds 2 register columns (w, w+16); per round rotates
// them against smem columns q0=(w+r)&31 and q1=(q0+16)&31 (all 32 disjoint).
// Dirty flags skip writeback of untouched blocks (late sweeps are mostly clean).
__global__ void __launch_bounds__(512, 2) k_jacobi() {
    int c = blockIdx.x;
    float* Bg = g_B + (size_t)c * HW;
    int t = threadIdx.x, lane = t & 31, w = t >> 5;   // w in 0..15

    __shared__ float sj[8192];     // 32KB: one 32-column block
    __shared__ float snj[32];      // column norms^2 of smem block
    __shared__ int s_flag;         // any rotation this sweep
    __shared__ int s_dirty;        // any rotation this (bi,bj) phase
    __shared__ int s_any;          // any rotation this bi iteration

    for (int sweep = 0; sweep < NSWMAX; sweep++) {
        if (t == 0) s_flag = 0;
        __syncthreads();
        for (int bi = 0; bi < 8; bi++) {
            // ---- load block bi: warp w loads cols w, w+16 + computes norms
#pragma unroll
            for (int h = 0; h < 2; h++) {
                int col = w + 16 * h;
                const float4* src = (const float4*)(Bg + (bi * 32 + col) * 256);
                float4* dst = (float4*)(sj + col * 256);
                float4 v0 = src[lane * 2], v1 = src[lane * 2 + 1];
                dst[lane * 2] = v0; dst[lane * 2 + 1] = v1;
                float a = v0.x*v0.x + v0.y*v0.y + v0.z*v0.z + v0.w*v0.w
                        + v1.x*v1.x + v1.y*v1.y + v1.z*v1.z + v1.w*v1.w;
                a = warp_sum(a);
                if (lane == 0) snj[col] = a;
            }
            if (t == 0) s_any = 0;
            __syncthreads();
            // ---- intra-block tournament: 31 rounds x 16 pairs
            for (int r = 0; r < 31; r++) {
                int p = (w == 0) ? 0 : 1 + (w - 1 + r) % 31;
                int q = 1 + (30 - w + r) % 31;
                float4* cp = (float4*)(sj + p * 256);
                float4* cq = (float4*)(sj + q * 256);
                float4 p0 = cp[lane * 2], p1 = cp[lane * 2 + 1];
                float4 q0 = cq[lane * 2], q1 = cq[lane * 2 + 1];
                float apq = p0.x * q0.x;
                apq = fmaf(p0.y, q0.y, apq);
                apq = fmaf(p0.z, q0.z, apq);
                apq = fmaf(p0.w, q0.w, apq);
                apq = fmaf(p1.x, q1.x, apq);
                apq = fmaf(p1.y, q1.y, apq);
                apq = fmaf(p1.z, q1.z, apq);
                apq = fmaf(p1.w, q1.w, apq);
                apq = warp_sum(apq);
                float app = snj[p], aqq = snj[q];
                if (apq * apq > ROTTHR * app * aqq) {
                    float tau = (aqq - app) / (2.0f * apq);
                    float tt  = copysignf(1.0f, tau) / (fabsf(tau) + sqrtf(1.0f + tau * tau));
                    float cth = 1.0f / sqrtf(1.0f + tt * tt);
                    float sth = tt * cth;
                    float4 np, nq;
                    np.x = cth*p0.x - sth*q0.x;  nq.x = sth*p0.x + cth*q0.x;
                    np.y = cth*p0.y - sth*q0.y;  nq.y = sth*p0.y + cth*q0.y;
                    np.z = cth*p0.z - sth*q0.z;  nq.z = sth*p0.z + cth*q0.z;
                    np.w = cth*p0.w - sth*q0.w;  nq.w = sth*p0.w + cth*q0.w;
                    cp[lane * 2] = np;  cq[lane * 2] = nq;
                    np.x = cth*p1.x - sth*q1.x;  nq.x = sth*p1.x + cth*q1.x;
                    np.y = cth*p1.y - sth*q1.y;  nq.y = sth*p1.y + cth*q1.y;
                    np.z = cth*p1.z - sth*q1.z;  nq.z = sth*p1.z + cth*q1.z;
                    np.w = cth*p1.w - sth*q1.w;  nq.w = sth*p1.w + cth*q1.w;
                    cp[lane * 2 + 1] = np;  cq[lane * 2 + 1] = nq;
                    if (lane == 0) {
                        snj[p] = app - tt * apq;
                        snj[q] = aqq + tt * apq;
                        s_flag = 1; s_any = 1;
                    }
                }
                __syncthreads();
            }
            // ---- move cols w and w+16 of bi into registers (exact norms)
            float rp0[8], rp1[8], app0, app1;
            {
                const float4* c0 = (const float4*)(sj + w * 256);
                float4 a0 = c0[lane * 2], a1 = c0[lane * 2 + 1];
                rp0[0]=a0.x; rp0[1]=a0.y; rp0[2]=a0.z; rp0[3]=a0.w;
                rp0[4]=a1.x; rp0[5]=a1.y; rp0[6]=a1.z; rp0[7]=a1.w;
                float a = 0.f;
#pragma unroll
                for (int m = 0; m < 8; m++) a = fmaf(rp0[m], rp0[m], a);
                app0 = warp_sum(a);
                const float4* c1 = (const float4*)(sj + (w + 16) * 256);
                float4 b0 = c1[lane * 2], b1 = c1[lane * 2 + 1];
                rp1[0]=b0.x; rp1[1]=b0.y; rp1[2]=b0.z; rp1[3]=b0.w;
                rp1[4]=b1.x; rp1[5]=b1.y; rp1[6]=b1.z; rp1[7]=b1.w;
                float b = 0.f;
#pragma unroll
                for (int m = 0; m < 8; m++) b = fmaf(rp1[m], rp1[m], b);
                app1 = warp_sum(b);
            }
            // ---- cross-block phase
            for (int bj = bi + 1; bj < 8; bj++) {
                // load bj (own cols — same-warp ordering vs. prior reads)
#pragma unroll
                for (int h = 0; h < 2; h++) {
                    int col = w + 16 * h;
                    const float4* src = (const float4*)(Bg + (bj * 32 + col) * 256);
                    float4* dst = (float4*)(sj + col * 256);
                    float4 v0 = src[lane * 2], v1 = src[lane * 2 + 1];
                    dst[lane * 2] = v0; dst[lane * 2 + 1] = v1;
                    float a = v0.x*v0.x + v0.y*v0.y + v0.z*v0.z + v0.w*v0.w
                            + v1.x*v1.x + v1.y*v1.y + v1.z*v1.z + v1.w*v1.w;
                    a = warp_sum(a);
                    if (lane == 0) snj[col] = a;
                }
                if (t == 0) s_dirty = 0;
                __syncthreads();
                for (int r = 0; r < 32; r++) {
                    int q0i = (w + r) & 31;
                    int q1i = (q0i + 16) & 31;
                    float4* cq0 = (float4*)(sj + q0i * 256);
                    float4* cq1 = (float4*)(sj + q1i * 256);
                    float4 x0 = cq0[lane * 2], x1 = cq0[lane * 2 + 1];
                    float4 y0 = cq1[lane * 2], y1 = cq1[lane * 2 + 1];
                    float bq0[8] = {x0.x,x0.y,x0.z,x0.w,x1.x,x1.y,x1.z,x1.w};
                    float bq1[8] = {y0.x,y0.y,y0.z,y0.w,y1.x,y1.y,y1.z,y1.w};
                    float d0 = 0.f, d1 = 0.f;
#pragma unroll
                    for (int m = 0; m < 8; m++) {
                        d0 = fmaf(rp0[m], bq0[m], d0);
                        d1 = fmaf(rp1[m], bq1[m], d1);
                    }
#pragma unroll
                    for (int o = 16; o > 0; o >>= 1) {   // interleaved chains
                        d0 += __shfl_xor_sync(0xFFFFFFFFu, d0, o);
                        d1 += __shfl_xor_sync(0xFFFFFFFFu, d1, o);
                    }
                    float aqq0 = snj[q0i], aqq1 = snj[q1i];
                    if (d0 * d0 > ROTTHR * app0 * aqq0) {
                        float tau = (aqq0 - app0) / (2.0f * d0);
                        float tt  = copysignf(1.0f, tau) / (fabsf(tau) + sqrtf(1.0f + tau * tau));
                        float cth = 1.0f / sqrtf(1.0f + tt * tt);
                        float sth = tt * cth;
                        float4 nv;
                        nv.x = fmaf(sth, rp0[0], cth * bq0[0]);
                        nv.y = fmaf(sth, rp0[1], cth * bq0[1]);
                        nv.z = fmaf(sth, rp0[2], cth * bq0[2]);
                        nv.w = fmaf(sth, rp0[3], cth * bq0[3]);
                        cq0[lane * 2] = nv;
                        nv.x = fmaf(sth, rp0[4], cth * bq0[4]);
                        nv.y = fmaf(sth, rp0[5], cth * bq0[5]);
                        nv.z = fmaf(sth, rp0[6], cth * bq0[6]);
                        nv.w = fmaf(sth, rp0[7], cth * bq0[7]);
                        cq0[lane * 2 + 1] = nv;
#pragma unroll
                        for (int m = 0; m < 8; m++)
                            rp0[m] = fmaf(cth, rp0[m], -sth * bq0[m]);
                        app0 = app0 - tt * d0;
                        if (lane == 0) { snj[q0i] = aqq0 + tt * d0; s_flag = 1; s_dirty = 1; s_any = 1; }
                    }
                    if (d1 * d1 > ROTTHR * app1 * aqq1) {
                        float tau = (aqq1 - app1) / (2.0f * d1);
                        float tt  = copysignf(1.0f, tau) / (fabsf(tau) + sqrtf(1.0f + tau * tau));
                        float cth = 1.0f / sqrtf(1.0f + tt * tt);
                        float sth = tt * cth;
                        float4 nv;
                        nv.x = fmaf(sth, rp1[0], cth * bq1[0]);
                        nv.y = fmaf(sth, rp1[1], cth * bq1[1]);
                        nv.z = fmaf(sth, rp1[2], cth * bq1[2]);
                        nv.w = fmaf(sth, rp1[3], cth * bq1[3]);
                        cq1[lane * 2] = nv;
                        nv.x = fmaf(sth, rp1[4], cth * bq1[4]);
                        nv.y = fmaf(sth, rp1[5], cth * bq1[5]);
                        nv.z = fmaf(sth, rp1[6], cth * bq1[6]);
                        nv.w = fmaf(sth, rp1[7], cth * bq1[7]);
                        cq1[lane * 2 + 1] = nv;
#pragma unroll
                        for (int m = 0; m < 8; m++)
                            rp1[m] = fmaf(cth, rp1[m], -sth * bq1[m]);
                        app1 = app1 - tt * d1;
                        if (lane == 0) { snj[q1i] = aqq1 + tt * d1; s_flag = 1; s_dirty = 1; s_any = 1; }
                    }
                    __syncthreads();
                }
                // store bj back only if some rotation touched it this phase
                if (s_dirty) {
#pragma unroll
                    for (int h = 0; h < 2; h++) {
                        int col = w + 16 * h;
                        float4* dst = (float4*)(Bg + (bj * 32 + col) * 256);
                        const float4* src = (const float4*)(sj + col * 256);
                        dst[lane * 2] = src[lane * 2];
                        dst[lane * 2 + 1] = src[lane * 2 + 1];
                    }
                }
            }
            // ---- store register columns back only if bi iteration rotated at all
            if (s_any) {
                ((float4*)(Bg + (bi * 32 + w) * 256))[lane * 2] =
                    make_float4(rp0[0], rp0[1], rp0[2], rp0[3]);
                ((float4*)(Bg + (bi * 32 + w) * 256))[lane * 2 + 1] =
                    make_float4(rp0[4], rp0[5], rp0[6], rp0[7]);
                ((float4*)(Bg + (bi * 32 + w + 16) * 256))[lane * 2] =
                    make_float4(rp1[0], rp1[1], rp1[2], rp1[3]);
                ((float4*)(Bg + (bi * 32 + w + 16) * 256))[lane * 2 + 1] =
                    make_float4(rp1[4], rp1[5], rp1[6], rp1[7]);
            }
            __syncthreads();
        }
        __syncthreads();
        int done = (s_flag == 0);
        __syncthreads();
        if (done) break;
    }
}

// ---------------- stage 4: column norms, rank, keep factor ----------------
__global__ void k_fact() {
    int c = blockIdx.x, t = threadIdx.x, lane = t & 31, w = t >> 5;
    __shared__ float s2[256];
    const float* B = g_B + (size_t)c * HW;
    for (int j = w; j < 256; j += 8) {
        const float* col = B + j * 256;
        float a = 0.f;
#pragma unroll
        for (int m = 0; m < 8; m++) {
            float v = col[lane + 32 * m];
            a = fmaf(v, v, a);
        }
        a = warp_sum(a);
        if (lane == 0) s2[j] = a;
    }
    __syncthreads();
    float mys = s2[t];
    int kc = g_k[c];
    int rank = 0;
    for (int j = 0; j < 256; j++) {
        float v = s2[j];
        rank += (v > mys) || (v == mys && j < t);
    }
    g_fact[c * 256 + t] = (rank < kc) ? 1.0f / fmaxf(mys, 1e-20f) : 0.0f;
}

// ---------------- stage 5: T = diag(f) * B^T A  (C = M*N, M row-major = B^T) ----------
__global__ void __launch_bounds__(256) k_gemmT(const float* __restrict__ x) {
    int c = blockIdx.z;
    const float* M = g_B + (size_t)c * HW;   // M[j][i] = B(i,j)
    const float* N = x + (size_t)c * HW;     // A row-major
    float* C = g_T + (size_t)c * HW;
    int m0 = blockIdx.y * 64, n0 = blockIdx.x * 64;
    __shared__ float Ms[16][68], Ns[16][68];
    int t = threadIdx.x;
    int tx = t & 15, ty = t >> 4;
    float acc[4][4] = {};
    for (int k0 = 0; k0 < 256; k0 += 16) {
#pragma unroll
        for (int u = 0; u < 4; u++) {
            int id = t + 256 * u;
            int kk = id & 15, mm = id >> 4;
            Ms[kk][mm] = M[(m0 + mm) * 256 + k0 + kk];
        }
#pragma unroll
        for (int u = 0; u < 4; u++) {
            int id = t + 256 * u;
            int kk = id >> 6, nn = id & 63;
            Ns[kk][nn] = N[(k0 + kk) * 256 + n0 + nn];
        }
        __syncthreads();
#pragma unroll
        for (int kk = 0; kk < 16; kk++) {
            float a[4], b[4];
#pragma unroll
            for (int i = 0; i < 4; i++) a[i] = Ms[kk][ty * 4 + i];
#pragma unroll
            for (int j = 0; j < 4; j++) b[j] = Ns[kk][tx * 4 + j];
#pragma unroll
            for (int i = 0; i < 4; i++)
#pragma unroll
                for (int j = 0; j < 4; j++) acc[i][j] = fmaf(a[i], b[j], acc[i][j]);
        }
        __syncthreads();
    }
    const float* f = g_fact + c * 256;
#pragma unroll
    for (int i = 0; i < 4; i++) {
        float fi = f[m0 + ty * 4 + i];
#pragma unroll
        for (int j = 0; j < 4; j++)
            C[(m0 + ty * 4 + i) * 256 + n0 + tx * 4 + j] = acc[i][j] * fi;
    }
}

// ---------------- stage 6: R = B * T  (= M^T * N with M as above) ----------------
__global__ void __launch_bounds__(256) k_gemmR() {
    int c = blockIdx.z;
    const float* M = g_B + (size_t)c * HW;   // M[j][i] = B(i,j); need M^T * T
    const float* N = g_T + (size_t)c * HW;
    float* C = g_R + (size_t)c * HW;
    int m0 = blockIdx.y * 64, n0 = blockIdx.x * 64;
    __shared__ float Ms[16][68], Ns[16][68];
    int t = threadIdx.x;
    int tx = t & 15, ty = t >> 4;
    float acc[4][4] = {};
    for (int k0 = 0; k0 < 256; k0 += 16) {
#pragma unroll
        for (int u = 0; u < 4; u++) {
            int id = t + 256 * u;
            int kk = id >> 6, mm = id & 63;
            Ms[kk][mm] = M[(k0 + kk) * 256 + m0 + mm];   // M^T tile, coalesced
        }
#pragma unroll
        for (int u = 0; u < 4; u++) {
            int id = t + 256 * u;
            int kk = id >> 6, nn = id & 63;
            Ns[kk][nn] = N[(k0 + kk) * 256 + n0 + nn];
        }
        __syncthreads();
#pragma unroll
        for (int kk = 0; kk < 16; kk++) {
            float a[4], b[4];
#pragma unroll
            for (int i = 0; i < 4; i++) a[i] = Ms[kk][ty * 4 + i];
#pragma unroll
            for (int j = 0; j < 4; j++) b[j] = Ns[kk][tx * 4 + j];
#pragma unroll
            for (int i = 0; i < 4; i++)
#pragma unroll
                for (int j = 0; j < 4; j++) acc[i][j] = fmaf(a[i], b[j], acc[i][j]);
        }
        __syncthreads();
    }
#pragma unroll
    for (int i = 0; i < 4; i++)
#pragma unroll
        for (int j = 0; j < 4; j++)
            C[(m0 + ty * 4 + i) * 256 + n0 + tx * 4 + j] = acc[i][j];
}

// ---------------- stage 7: channel mean & max of recon ----------------
__global__ void k_avgmax() {
    int pix = blockIdx.x * 1024 + threadIdx.x;
    float s = 0.f, m = -3.4e38f;
    for (int c = 0; c < 256; c++) {
        float v = g_R[(size_t)c * HW + pix];
        s += v;
        m = fmaxf(m, v);
    }
    g_cat[pix]      = s * (1.0f / 256.0f);
    g_cat[HW + pix] = m;
}

// ---------------- stage 8: 7x7 conv (pad 3) + EPS clamp + sigmoid ----------------
__global__ void k_conv(const float* __restrict__ cw, float* __restrict__ out) {
    __shared__ float wsm[98];
    int tx = threadIdx.x, ty = threadIdx.y;
    int tid = ty * 32 + tx;
    if (tid < 98) wsm[tid] = cw[tid];
    __syncthreads();
    int gx = blockIdx.x * 32 + tx;
    int gy = blockIdx.y * 8 + ty;
    float acc = 0.f;
#pragma unroll
    for (int ci = 0; ci < 2; ci++) {
#pragma unroll
        for (int kh = 0; kh < 7; kh++) {
            int iy = gy + kh - 3;
            if (iy < 0 || iy > 255) continue;
#pragma unroll
            for (int kw = 0; kw < 7; kw++) {
                int ix = gx + kw - 3;
                if (ix < 0 || ix > 255) continue;
                acc = fmaf(g_cat[ci * HW + iy * 256 + ix], wsm[ci * 49 + kh * 7 + kw], acc);
            }
        }
    }
    const float EPSF = 2.220446049250313e-16f;
    if (acc < EPSF) acc = EPSF;
    out[gy * 256 + gx] = 1.0f / (1.0f + expf(-acc));
}

// ---------------- launch ----------------
extern "C" void kernel_launch(void* const* d_in, const int* in_sizes, int n_in,
                              void* d_out, int out_size) {
    const float* x  = (const float*)d_in[0];
    const float* w1 = (const float*)d_in[1];
    const float* w2 = (const float*)d_in[2];
    const float* cw = (const float*)d_in[3];
    const int*   kv = (const int*)d_in[4];

    k_stats<<<256, 256>>>(x);
    k_att<<<1, 256>>>(w1, w2, kv);
    k_tr<<<dim3(8, 8, 256), dim3(32, 8)>>>(x);
    k_jacobi<<<256, 512>>>();
    k_fact<<<256, 256>>>();
    k_gemmT<<<dim3(4, 4, 256), 256>>>(x);
    k_gemmR<<<dim3(4, 4, 256), 256>>>();
    k_avgmax<<<64, 1024>>>();
    k_conv<<<dim3(8, 32), dim3(32, 8)>>>(cw, (float*)d_out);
}

// round 13
// speedup vs baseline: 1.4410x; 1.0310x over previous
#include <cuda_runtime.h>
#include <math.h>

#define CC 256
#define HW 65536
#define NSWMAX 10
#define ROTTHR 1e-7f   // relative off-diag threshold^2

// ---- scratch (static device arrays; no allocation anywhere) ----
__device__ float g_B[CC * HW];   // 64MB: per-channel working matrix, column-major
__device__ float g_T[CC * HW];   // 64MB: T = diag(f) * B^T A
__device__ float g_R[CC * HW];   // 64MB: recon = B * T
__device__ float g_mean[CC];
__device__ float g_max[CC];
__device__ int   g_k[CC];
__device__ float g_fact[CC * CC];
__device__ float g_cat[2 * HW];

__device__ __forceinline__ float warp_sum(float a) {
#pragma unroll
    for (int o = 16; o > 0; o >>= 1) a += __shfl_xor_sync(0xFFFFFFFFu, a, o);
    return a;
}

// ---------------- stage 0: per-channel mean & max over HxW ----------------
__global__ void k_stats(const float* __restrict__ x) {
    int c = blockIdx.x, t = threadIdx.x;
    const float* xc = x + (size_t)c * HW;
    double s = 0.0;
    float m = -3.4e38f;
    for (int i = t; i < HW; i += 256) {
        float v = xc[i];
        s += (double)v;
        m = fmaxf(m, v);
    }
    __shared__ double ss[256];
    __shared__ float  sm[256];
    ss[t] = s; sm[t] = m;
    __syncthreads();
    for (int o = 128; o > 0; o >>= 1) {
        if (t < o) { ss[t] += ss[t + o]; sm[t] = fmaxf(sm[t], sm[t + o]); }
        __syncthreads();
    }
    if (t == 0) {
        g_mean[c] = (float)(ss[0] / (double)HW);
        g_max[c]  = sm[0];
    }
}

// ---------------- stage 1: channel attention -> k[c] ----------------
__global__ void k_att(const float* __restrict__ w1, const float* __restrict__ w2,
                      const int* __restrict__ kvp) {
    int t = threadIdx.x;
    __shared__ float  mu[256], mx[256];
    __shared__ double hA[16], hM[16];
    __shared__ double sy[256];
    __shared__ double ymin, ymax;
    mu[t] = g_mean[t]; mx[t] = g_max[t];
    __syncthreads();
    if (t < 16) {
        double a = 0.0, b = 0.0;
        for (int c2 = 0; c2 < 256; c2++) {
            double w = (double)w1[t * 256 + c2];
            a += w * (double)mu[c2];
            b += w * (double)mx[c2];
        }
        hA[t] = a > 0.0 ? a : 0.0;   // relu
        hM[t] = b > 0.0 ? b : 0.0;
    }
    __syncthreads();
    {
        double acc = 0.0;
        for (int r = 0; r < 16; r++)
            acc += (double)w2[t * 16 + r] * (hA[r] + hM[r]);
        sy[t] = 1.0 / (1.0 + exp(-acc));     // sigmoid(y_avg + y_max)
    }
    __syncthreads();
    if (t == 0) {
        double mn = sy[0], mv = sy[0];
        for (int i = 1; i < 256; i++) { mn = fmin(mn, sy[i]); mv = fmax(mv, sy[i]); }
        ymin = mn; ymax = mv;
    }
    __syncthreads();
    // kv hedge: accept int32 or float32 bit patterns
    int iv = *kvp;
    float fv = __int_as_float(iv);
    double kvd = (iv >= 0 && iv <= 1000000) ? (double)iv : (double)fv;
    double yc = (sy[t] - ymin) / (ymax - ymin + 1e-20);
    int k = (int)floor(256.0 * kvd * yc);
    if (k < 0) k = 0;
    if (k > 256) k = 256;
    g_k[t] = k;
}

// ---------------- stage 2: transpose x -> column-major B ----------------
__global__ void k_tr(const float* __restrict__ x) {
    __shared__ float tile[32][33];
    int c = blockIdx.z;
    int i0 = blockIdx.y * 32, j0 = blockIdx.x * 32;
    int tx = threadIdx.x, ty = threadIdx.y;
    const float* xc = x + (size_t)c * HW;
    float* bc = g_B + (size_t)c * HW;
#pragma unroll
    for (int m = 0; m < 4; m++)
        tile[ty + 8 * m][tx] = xc[(i0 + ty + 8 * m) * 256 + j0 + tx];
    __syncthreads();
#pragma unroll
    for (int m = 0; m < 4; m++)
        bc[(j0 + ty + 8 * m) * 256 + i0 + tx] = tile[tx][ty + 8 * m];
}

// ---------------- stage 3: blocked one-sided Jacobi (Hestenes), no V ----------------
// 512 threads (16 warps), 2 CTAs/SM. 8 blocks of 32 columns.
// Intra-block: 31 tournament rounds x 16 warp-pairs in smem, cached norms.
// Cross-block: each warp holds 2 register columns (w, w+16); per round rotates
// them against smem columns q0=(w+r)&31 and q1=(q0+16)&31 (all 32 disjoint).
// Clean-pair matrix (persistent in smem) skips fully-converged block pairs:
// a phase with zero rotations is marked clean; any rotation involving a block
// invalidates all pairs containing that block. Clean phases cost nothing.
__global__ void __launch_bounds__(512, 2) k_jacobi() {
    int c = blockIdx.x;
    float* Bg = g_B + (size_t)c * HW;
    int t = threadIdx.x, lane = t & 31, w = t >> 5;   // w in 0..15

    __shared__ float sj[8192];     // 32KB: one 32-column block
    __shared__ float snj[32];      // column norms^2 of smem block
    __shared__ int s_flag;         // any rotation this sweep
    __shared__ int s_dirty;        // any rotation this phase
    __shared__ int s_any;          // any rotation this bi iteration
    __shared__ int s_skip;         // whole bi iteration clean
    __shared__ unsigned char s_clean[8][8];

    if (t < 64) s_clean[t >> 3][t & 7] = 0;
    __syncthreads();

    for (int sweep = 0; sweep < NSWMAX; sweep++) {
        if (t == 0) s_flag = 0;
        __syncthreads();
        for (int bi = 0; bi < 8; bi++) {
            // ---- whole-iteration skip check
            if (t == 0) {
                int ac = s_clean[bi][bi];
                for (int bj = bi + 1; bj < 8; bj++) ac &= s_clean[bi][bj];
                s_skip = ac;
            }
            __syncthreads();
            if (s_skip) continue;   // uniform

            // ---- load block bi: warp w loads cols w, w+16 + computes norms
#pragma unroll
            for (int h = 0; h < 2; h++) {
                int col = w + 16 * h;
                const float4* src = (const float4*)(Bg + (bi * 32 + col) * 256);
                float4* dst = (float4*)(sj + col * 256);
                float4 v0 = src[lane * 2], v1 = src[lane * 2 + 1];
                dst[lane * 2] = v0; dst[lane * 2 + 1] = v1;
                float a = v0.x*v0.x + v0.y*v0.y + v0.z*v0.z + v0.w*v0.w
                        + v1.x*v1.x + v1.y*v1.y + v1.z*v1.z + v1.w*v1.w;
                a = warp_sum(a);
                if (lane == 0) snj[col] = a;
            }
            if (t == 0) { s_any = 0; s_dirty = 0; }
            __syncthreads();

            // ---- intra-block tournament (only if not converged)
            int do_intra = (s_clean[bi][bi] == 0);   // uniform, stable
            if (do_intra) {
                for (int r = 0; r < 31; r++) {
                    int p = (w == 0) ? 0 : 1 + (w - 1 + r) % 31;
                    int q = 1 + (30 - w + r) % 31;
                    float4* cp = (float4*)(sj + p * 256);
                    float4* cq = (float4*)(sj + q * 256);
                    float4 p0 = cp[lane * 2], p1 = cp[lane * 2 + 1];
                    float4 q0 = cq[lane * 2], q1 = cq[lane * 2 + 1];
                    float apq = p0.x * q0.x;
                    apq = fmaf(p0.y, q0.y, apq);
                    apq = fmaf(p0.z, q0.z, apq);
                    apq = fmaf(p0.w, q0.w, apq);
                    apq = fmaf(p1.x, q1.x, apq);
                    apq = fmaf(p1.y, q1.y, apq);
                    apq = fmaf(p1.z, q1.z, apq);
                    apq = fmaf(p1.w, q1.w, apq);
                    apq = warp_sum(apq);
                    float app = snj[p], aqq = snj[q];
                    if (apq * apq > ROTTHR * app * aqq) {
                        float tau = (aqq - app) / (2.0f * apq);
                        float tt  = copysignf(1.0f, tau) / (fabsf(tau) + sqrtf(1.0f + tau * tau));
                        float cth = 1.0f / sqrtf(1.0f + tt * tt);
                        float sth = tt * cth;
                        float4 np, nq;
                        np.x = cth*p0.x - sth*q0.x;  nq.x = sth*p0.x + cth*q0.x;
                        np.y = cth*p0.y - sth*q0.y;  nq.y = sth*p0.y + cth*q0.y;
                        np.z = cth*p0.z - sth*q0.z;  nq.z = sth*p0.z + cth*q0.z;
                        np.w = cth*p0.w - sth*q0.w;  nq.w = sth*p0.w + cth*q0.w;
                        cp[lane * 2] = np;  cq[lane * 2] = nq;
                        np.x = cth*p1.x - sth*q1.x;  nq.x = sth*p1.x + cth*q1.x;
                        np.y = cth*p1.y - sth*q1.y;  nq.y = sth*p1.y + cth*q1.y;
                        np.z = cth*p1.z - sth*q1.z;  nq.z = sth*p1.z + cth*q1.z;
                        np.w = cth*p1.w - sth*q1.w;  nq.w = sth*p1.w + cth*q1.w;
                        cp[lane * 2 + 1] = np;  cq[lane * 2 + 1] = nq;
                        if (lane == 0) {
                            snj[p] = app - tt * apq;
                            snj[q] = aqq + tt * apq;
                            s_flag = 1; s_any = 1; s_dirty = 1;
                        }
                    }
                    __syncthreads();
                }
                // clean-matrix update from intra result (s_dirty stable: post-barrier)
                if (t == 0) {
                    if (s_dirty) {
                        for (int k2 = 0; k2 < 8; k2++) { s_clean[bi][k2] = 0; s_clean[k2][bi] = 0; }
                    } else {
                        s_clean[bi][bi] = 1;
                    }
                }
                // settled by the barrier at top of bj loop below
            }

            // ---- move cols w and w+16 of bi into registers (exact norms)
            float rp0[8], rp1[8], app0, app1;
            {
                const float4* c0 = (const float4*)(sj + w * 256);
                float4 a0 = c0[lane * 2], a1 = c0[lane * 2 + 1];
                rp0[0]=a0.x; rp0[1]=a0.y; rp0[2]=a0.z; rp0[3]=a0.w;
                rp0[4]=a1.x; rp0[5]=a1.y; rp0[6]=a1.z; rp0[7]=a1.w;
                float a = 0.f;
#pragma unroll
                for (int m = 0; m < 8; m++) a = fmaf(rp0[m], rp0[m], a);
                app0 = warp_sum(a);
                const float4* c1 = (const float4*)(sj + (w + 16) * 256);
                float4 b0 = c1[lane * 2], b1 = c1[lane * 2 + 1];
                rp1[0]=b0.x; rp1[1]=b0.y; rp1[2]=b0.z; rp1[3]=b0.w;
                rp1[4]=b1.x; rp1[5]=b1.y; rp1[6]=b1.z; rp1[7]=b1.w;
                float b = 0.f;
#pragma unroll
                for (int m = 0; m < 8; m++) b = fmaf(rp1[m], rp1[m], b);
                app1 = warp_sum(b);
            }

            // ---- cross-block phases
            for (int bj = bi + 1; bj < 8; bj++) {
                __syncthreads();   // settle clean-matrix writes from prior phase/intra
                int do_cross = (s_clean[bi][bj] == 0);   // uniform
                if (!do_cross) continue;

                // load bj (own cols — same-warp ordering vs. prior reads)
#pragma unroll
                for (int h = 0; h < 2; h++) {
                    int col = w + 16 * h;
                    const float4* src = (const float4*)(Bg + (bj * 32 + col) * 256);
                    float4* dst = (float4*)(sj + col * 256);
                    float4 v0 = src[lane * 2], v1 = src[lane * 2 + 1];
                    dst[lane * 2] = v0; dst[lane * 2 + 1] = v1;
                    float a = v0.x*v0.x + v0.y*v0.y + v0.z*v0.z + v0.w*v0.w
                            + v1.x*v1.x + v1.y*v1.y + v1.z*v1.z + v1.w*v1.w;
                    a = warp_sum(a);
                    if (lane == 0) snj[col] = a;
                }
                if (t == 0) s_dirty = 0;
                __syncthreads();

                for (int r = 0; r < 32; r++) {
                    int q0i = (w + r) & 31;
                    int q1i = (q0i + 16) & 31;
                    float4* cq0 = (float4*)(sj + q0i * 256);
                    float4* cq1 = (float4*)(sj + q1i * 256);
                    float4 x0 = cq0[lane * 2], x1 = cq0[lane * 2 + 1];
                    float4 y0 = cq1[lane * 2], y1 = cq1[lane * 2 + 1];
                    float bq0[8] = {x0.x,x0.y,x0.z,x0.w,x1.x,x1.y,x1.z,x1.w};
                    float bq1[8] = {y0.x,y0.y,y0.z,y0.w,y1.x,y1.y,y1.z,y1.w};
                    float d0 = 0.f, d1 = 0.f;
#pragma unroll
                    for (int m = 0; m < 8; m++) {
                        d0 = fmaf(rp0[m], bq0[m], d0);
                        d1 = fmaf(rp1[m], bq1[m], d1);
                    }
#pragma unroll
                    for (int o = 16; o > 0; o >>= 1) {   // interleaved chains
                        d0 += __shfl_xor_sync(0xFFFFFFFFu, d0, o);
                        d1 += __shfl_xor_sync(0xFFFFFFFFu, d1, o);
                    }
                    float aqq0 = snj[q0i], aqq1 = snj[q1i];
                    if (d0 * d0 > ROTTHR * app0 * aqq0) {
                        float tau = (aqq0 - app0) / (2.0f * d0);
                        float tt  = copysignf(1.0f, tau) / (fabsf(tau) + sqrtf(1.0f + tau * tau));
                        float cth = 1.0f / sqrtf(1.0f + tt * tt);
                        float sth = tt * cth;
                        float4 nv;
                        nv.x = fmaf(sth, rp0[0], cth * bq0[0]);
                        nv.y = fmaf(sth, rp0[1], cth * bq0[1]);
                        nv.z = fmaf(sth, rp0[2], cth * bq0[2]);
                        nv.w = fmaf(sth, rp0[3], cth * bq0[3]);
                        cq0[lane * 2] = nv;
                        nv.x = fmaf(sth, rp0[4], cth * bq0[4]);
                        nv.y = fmaf(sth, rp0[5], cth * bq0[5]);
                        nv.z = fmaf(sth, rp0[6], cth * bq0[6]);
                        nv.w = fmaf(sth, rp0[7], cth * bq0[7]);
                        cq0[lane * 2 + 1] = nv;
#pragma unroll
                        for (int m = 0; m < 8; m++)
                            rp0[m] = fmaf(cth, rp0[m], -sth * bq0[m]);
                        app0 = app0 - tt * d0;
                        if (lane == 0) { snj[q0i] = aqq0 + tt * d0; s_flag = 1; s_dirty = 1; s_any = 1; }
                    }
                    if (d1 * d1 > ROTTHR * app1 * aqq1) {
                        float tau = (aqq1 - app1) / (2.0f * d1);
                        float tt  = copysignf(1.0f, tau) / (fabsf(tau) + sqrtf(1.0f + tau * tau));
                        float cth = 1.0f / sqrtf(1.0f + tt * tt);
                        float sth = tt * cth;
                        float4 nv;
                        nv.x = fmaf(sth, rp1[0], cth * bq1[0]);
                        nv.y = fmaf(sth, rp1[1], cth * bq1[1]);
                        nv.z = fmaf(sth, rp1[2], cth * bq1[2]);
                        nv.w = fmaf(sth, rp1[3], cth * bq1[3]);
                        cq1[lane * 2] = nv;
                        nv.x = fmaf(sth, rp1[4], cth * bq1[4]);
                        nv.y = fmaf(sth, rp1[5], cth * bq1[5]);
                        nv.z = fmaf(sth, rp1[6], cth * bq1[6]);
                        nv.w = fmaf(sth, rp1[7], cth * bq1[7]);
                        cq1[lane * 2 + 1] = nv;
#pragma unroll
                        for (int m = 0; m < 8; m++)
                            rp1[m] = fmaf(cth, rp1[m], -sth * bq1[m]);
                        app1 = app1 - tt * d1;
                        if (lane == 0) { snj[q1i] = aqq1 + tt * d1; s_flag = 1; s_dirty = 1; s_any = 1; }
                    }
                    __syncthreads();
                }
                // store bj back + clean bookkeeping (s_dirty stable post-barrier)
                if (s_dirty) {
#pragma unroll
                    for (int h = 0; h < 2; h++) {
                        int col = w + 16 * h;
                        float4* dst = (float4*)(Bg + (bj * 32 + col) * 256);
                        const float4* src = (const float4*)(sj + col * 256);
                        dst[lane * 2] = src[lane * 2];
                        dst[lane * 2 + 1] = src[lane * 2 + 1];
                    }
                    if (t == 0) {
                        for (int k2 = 0; k2 < 8; k2++) {
                            s_clean[bi][k2] = 0; s_clean[k2][bi] = 0;
                            s_clean[bj][k2] = 0; s_clean[k2][bj] = 0;
                        }
                    }
                } else {
                    if (t == 0) { s_clean[bi][bj] = 1; s_clean[bj][bi] = 1; }
                }
                // settled by barrier at top of next bj iteration (or bi-end barrier)
            }
            __syncthreads();   // settle last phase's clean writes + sj reads
            // ---- store register columns back only if bi iteration rotated at all
            if (s_any) {
                ((float4*)(Bg + (bi * 32 + w) * 256))[lane * 2] =
                    make_float4(rp0[0], rp0[1], rp0[2], rp0[3]);
                ((float4*)(Bg + (bi * 32 + w) * 256))[lane * 2 + 1] =
                    make_float4(rp0[4], rp0[5], rp0[6], rp0[7]);
                ((float4*)(Bg + (bi * 32 + w + 16) * 256))[lane * 2] =
                    make_float4(rp1[0], rp1[1], rp1[2], rp1[3]);
                ((float4*)(Bg + (bi * 32 + w + 16) * 256))[lane * 2 + 1] =
                    make_float4(rp1[4], rp1[5], rp1[6], rp1[7]);
            }
            __syncthreads();
        }
        __syncthreads();
        int done = (s_flag == 0);
        __syncthreads();
        if (done) break;
    }
}

// ---------------- stage 4: column norms, rank, keep factor ----------------
__global__ void k_fact() {
    int c = blockIdx.x, t = threadIdx.x, lane = t & 31, w = t >> 5;
    __shared__ float s2[256];
    const float* B = g_B + (size_t)c * HW;
    for (int j = w; j < 256; j += 8) {
        const float* col = B + j * 256;
        float a = 0.f;
#pragma unroll
        for (int m = 0; m < 8; m++) {
            float v = col[lane + 32 * m];
            a = fmaf(v, v, a);
        }
        a = warp_sum(a);
        if (lane == 0) s2[j] = a;
    }
    __syncthreads();
    float mys = s2[t];
    int kc = g_k[c];
    int rank = 0;
    for (int j = 0; j < 256; j++) {
        float v = s2[j];
        rank += (v > mys) || (v == mys && j < t);
    }
    g_fact[c * 256 + t] = (rank < kc) ? 1.0f / fmaxf(mys, 1e-20f) : 0.0f;
}

// ---------------- stage 5: T = diag(f) * B^T A  (C = M*N, M row-major = B^T) ----------
__global__ void __launch_bounds__(256) k_gemmT(const float* __restrict__ x) {
    int c = blockIdx.z;
    const float* M = g_B + (size_t)c * HW;   // M[j][i] = B(i,j)
    const float* N = x + (size_t)c * HW;     // A row-major
    float* C = g_T + (size_t)c * HW;
    int m0 = blockIdx.y * 64, n0 = blockIdx.x * 64;
    __shared__ float Ms[16][68], Ns[16][68];
    int t = threadIdx.x;
    int tx = t & 15, ty = t >> 4;
    float acc[4][4] = {};
    for (int k0 = 0; k0 < 256; k0 += 16) {
#pragma unroll
        for (int u = 0; u < 4; u++) {
            int id = t + 256 * u;
            int kk = id & 15, mm = id >> 4;
            Ms[kk][mm] = M[(m0 + mm) * 256 + k0 + kk];
        }
#pragma unroll
        for (int u = 0; u < 4; u++) {
            int id = t + 256 * u;
            int kk = id >> 6, nn = id & 63;
            Ns[kk][nn] = N[(k0 + kk) * 256 + n0 + nn];
        }
        __syncthreads();
#pragma unroll
        for (int kk = 0; kk < 16; kk++) {
            float a[4], b[4];
#pragma unroll
            for (int i = 0; i < 4; i++) a[i] = Ms[kk][ty * 4 + i];
#pragma unroll
            for (int j = 0; j < 4; j++) b[j] = Ns[kk][tx * 4 + j];
#pragma unroll
            for (int i = 0; i < 4; i++)
#pragma unroll
                for (int j = 0; j < 4; j++) acc[i][j] = fmaf(a[i], b[j], acc[i][j]);
        }
        __syncthreads();
    }
    const float* f = g_fact + c * 256;
#pragma unroll
    for (int i = 0; i < 4; i++) {
        float fi = f[m0 + ty * 4 + i];
#pragma unroll
        for (int j = 0; j < 4; j++)
            C[(m0 + ty * 4 + i) * 256 + n0 + tx * 4 + j] = acc[i][j] * fi;
    }
}

// ---------------- stage 6: R = B * T  (= M^T * N with M as above) ----------------
__global__ void __launch_bounds__(256) k_gemmR() {
    int c = blockIdx.z;
    const float* M = g_B + (size_t)c * HW;   // M[j][i] = B(i,j); need M^T * T
    const float* N = g_T + (size_t)c * HW;
    float* C = g_R + (size_t)c * HW;
    int m0 = blockIdx.y * 64, n0 = blockIdx.x * 64;
    __shared__ float Ms[16][68], Ns[16][68];
    int t = threadIdx.x;
    int tx = t & 15, ty = t >> 4;
    float acc[4][4] = {};
    for (int k0 = 0; k0 < 256; k0 += 16) {
#pragma unroll
        for (int u = 0; u < 4; u++) {
            int id = t + 256 * u;
            int kk = id >> 6, mm = id & 63;
            Ms[kk][mm] = M[(k0 + kk) * 256 + m0 + mm];   // M^T tile, coalesced
        }
#pragma unroll
        for (int u = 0; u < 4; u++) {
            int id = t + 256 * u;
            int kk = id >> 6, nn = id & 63;
            Ns[kk][nn] = N[(k0 + kk) * 256 + n0 + nn];
        }
        __syncthreads();
#pragma unroll
        for (int kk = 0; kk < 16; kk++) {
            float a[4], b[4];
#pragma unroll
            for (int i = 0; i < 4; i++) a[i] = Ms[kk][ty * 4 + i];
#pragma unroll
            for (int j = 0; j < 4; j++) b[j] = Ns[kk][tx * 4 + j];
#pragma unroll
            for (int i = 0; i < 4; i++)
#pragma unroll
                for (int j = 0; j < 4; j++) acc[i][j] = fmaf(a[i], b[j], acc[i][j]);
        }
        __syncthreads();
    }
#pragma unroll
    for (int i = 0; i < 4; i++)
#pragma unroll
        for (int j = 0; j < 4; j++)
            C[(m0 + ty * 4 + i) * 256 + n0 + tx * 4 + j] = acc[i][j];
}

// ---------------- stage 7: channel mean & max of recon ----------------
__global__ void k_avgmax() {
    int pix = blockIdx.x * 1024 + threadIdx.x;
    float s = 0.f, m = -3.4e38f;
    for (int c = 0; c < 256; c++) {
        float v = g_R[(size_t)c * HW + pix];
        s += v;
        m = fmaxf(m, v);
    }
    g_cat[pix]      = s * (1.0f / 256.0f);
    g_cat[HW + pix] = m;
}

// ---------------- stage 8: 7x7 conv (pad 3) + EPS clamp + sigmoid ----------------
__global__ void k_conv(const float* __restrict__ cw, float* __restrict__ out) {
    __shared__ float wsm[98];
    int tx = threadIdx.x, ty = threadIdx.y;
    int tid = ty * 32 + tx;
    if (tid < 98) wsm[tid] = cw[tid];
    __syncthreads();
    int gx = blockIdx.x * 32 + tx;
    int gy = blockIdx.y * 8 + ty;
    float acc = 0.f;
#pragma unroll
    for (int ci = 0; ci < 2; ci++) {
#pragma unroll
        for (int kh = 0; kh < 7; kh++) {
            int iy = gy + kh - 3;
            if (iy < 0 || iy > 255) continue;
#pragma unroll
            for (int kw = 0; kw < 7; kw++) {
                int ix = gx + kw - 3;
                if (ix < 0 || ix > 255) continue;
                acc = fmaf(g_cat[ci * HW + iy * 256 + ix], wsm[ci * 49 + kh * 7 + kw], acc);
            }
        }
    }
    const float EPSF = 2.220446049250313e-16f;
    if (acc < EPSF) acc = EPSF;
    out[gy * 256 + gx] = 1.0f / (1.0f + expf(-acc));
}

// ---------------- launch ----------------
extern "C" void kernel_launch(void* const* d_in, const int* in_sizes, int n_in,
                              void* d_out, int out_size) {
    const float* x  = (const float*)d_in[0];
    const float* w1 = (const float*)d_in[1];
    const float* w2 = (const float*)d_in[2];
    const float* cw = (const float*)d_in[3];
    const int*   kv = (const int*)d_in[4];

    k_stats<<<256, 256>>>(x);
    k_att<<<1, 256>>>(w1, w2, kv);
    k_tr<<<dim3(8, 8, 256), dim3(32, 8)>>>(x);
    k_jacobi<<<256, 512>>>();
    k_fact<<<256, 256>>>();
    k_gemmT<<<dim3(4, 4, 256), 256>>>(x);
    k_gemmR<<<dim3(4, 4, 256), 256>>>();
    k_avgmax<<<64, 1024>>>();
    k_conv<<<dim3(8, 32), dim3(32, 8)>>>(cw, (float*)d_out);
}

// round 14
// speedup vs baseline: 1.6888x; 1.1719x over previous
#include <cuda_runtime.h>
#include <math.h>

#define CC 256
#define HW 65536
#define NSWMAX 10
#define ROTTHR 2e-7f   // relative off-diag threshold^2

// ---- scratch (static device arrays; no allocation anywhere) ----
__device__ float g_B[CC * HW];   // 64MB: per-channel working matrix, column-major
__device__ float g_T[CC * HW];   // 64MB: T = diag(f) * B^T A
__device__ float g_R[CC * HW];   // 64MB: recon = B * T
__device__ float g_mean[CC];
__device__ float g_max[CC];
__device__ int   g_k[CC];
__device__ float g_fact[CC * CC];
__device__ float g_cat[2 * HW];

__device__ __forceinline__ float warp_sum(float a) {
#pragma unroll
    for (int o = 16; o > 0; o >>= 1) a += __shfl_xor_sync(0xFFFFFFFFu, a, o);
    return a;
}

// ---------------- stage 0: per-channel mean & max over HxW ----------------
__global__ void k_stats(const float* __restrict__ x) {
    int c = blockIdx.x, t = threadIdx.x;
    const float* xc = x + (size_t)c * HW;
    double s = 0.0;
    float m = -3.4e38f;
    for (int i = t; i < HW; i += 256) {
        float v = xc[i];
        s += (double)v;
        m = fmaxf(m, v);
    }
    __shared__ double ss[256];
    __shared__ float  sm[256];
    ss[t] = s; sm[t] = m;
    __syncthreads();
    for (int o = 128; o > 0; o >>= 1) {
        if (t < o) { ss[t] += ss[t + o]; sm[t] = fmaxf(sm[t], sm[t + o]); }
        __syncthreads();
    }
    if (t == 0) {
        g_mean[c] = (float)(ss[0] / (double)HW);
        g_max[c]  = sm[0];
    }
}

// ---------------- stage 1: channel attention -> k[c] ----------------
__global__ void k_att(const float* __restrict__ w1, const float* __restrict__ w2,
                      const int* __restrict__ kvp) {
    int t = threadIdx.x;
    __shared__ float  mu[256], mx[256];
    __shared__ double hA[16], hM[16];
    __shared__ double sy[256];
    __shared__ double ymin, ymax;
    mu[t] = g_mean[t]; mx[t] = g_max[t];
    __syncthreads();
    if (t < 16) {
        double a = 0.0, b = 0.0;
        for (int c2 = 0; c2 < 256; c2++) {
            double w = (double)w1[t * 256 + c2];
            a += w * (double)mu[c2];
            b += w * (double)mx[c2];
        }
        hA[t] = a > 0.0 ? a : 0.0;   // relu
        hM[t] = b > 0.0 ? b : 0.0;
    }
    __syncthreads();
    {
        double acc = 0.0;
        for (int r = 0; r < 16; r++)
            acc += (double)w2[t * 16 + r] * (hA[r] + hM[r]);
        sy[t] = 1.0 / (1.0 + exp(-acc));     // sigmoid(y_avg + y_max)
    }
    __syncthreads();
    if (t == 0) {
        double mn = sy[0], mv = sy[0];
        for (int i = 1; i < 256; i++) { mn = fmin(mn, sy[i]); mv = fmax(mv, sy[i]); }
        ymin = mn; ymax = mv;
    }
    __syncthreads();
    // kv hedge: accept int32 or float32 bit patterns
    int iv = *kvp;
    float fv = __int_as_float(iv);
    double kvd = (iv >= 0 && iv <= 1000000) ? (double)iv : (double)fv;
    double yc = (sy[t] - ymin) / (ymax - ymin + 1e-20);
    int k = (int)floor(256.0 * kvd * yc);
    if (k < 0) k = 0;
    if (k > 256) k = 256;
    g_k[t] = k;
}

// ---------------- stage 2: transpose x -> column-major B ----------------
__global__ void k_tr(const float* __restrict__ x) {
    __shared__ float tile[32][33];
    int c = blockIdx.z;
    int i0 = blockIdx.y * 32, j0 = blockIdx.x * 32;
    int tx = threadIdx.x, ty = threadIdx.y;
    const float* xc = x + (size_t)c * HW;
    float* bc = g_B + (size_t)c * HW;
#pragma unroll
    for (int m = 0; m < 4; m++)
        tile[ty + 8 * m][tx] = xc[(i0 + ty + 8 * m) * 256 + j0 + tx];
    __syncthreads();
#pragma unroll
    for (int m = 0; m < 4; m++)
        bc[(j0 + ty + 8 * m) * 256 + i0 + tx] = tile[tx][ty + 8 * m];
}

// rotate register pair (P owns app, Q owns aqq); returns t (tangent)
#define ROT_APPLY(RP, BQ, APP, AQQ, D)                                        \
    {                                                                         \
        float tau = ((AQQ) - (APP)) / (2.0f * (D));                           \
        float tt  = copysignf(1.0f, tau) / (fabsf(tau) + sqrtf(1.0f + tau * tau)); \
        float cth = 1.0f / sqrtf(1.0f + tt * tt);                             \
        float sth = tt * cth;                                                 \
        _Pragma("unroll")                                                     \
        for (int m = 0; m < 8; m++) {                                         \
            float xp = RP[m];                                                 \
            RP[m] = fmaf(cth, xp, -sth * BQ[m]);                              \
            BQ[m] = fmaf(sth, xp,  cth * BQ[m]);                              \
        }                                                                     \
        (APP) = (APP) - tt * (D);                                             \
        (AQQ) = (AQQ) + tt * (D);                                             \
    }

// ---------------- stage 3: blocked one-sided Jacobi (Hestenes), no V ----------------
// 512 threads (16 warps), 2 CTAs/SM. 8 blocks of 32 columns.
// Intra-block: 31 tournament rounds x 16 warp-pairs in smem, cached norms.
// Cross-block (pair-blocked, crossbar-halved): each warp holds 2 register
// columns (w, w+16). Per round it claims a PAIR of smem columns
// (q0=2*qp, q1=2*qp+1, qp=(w+r)&15), loads both into registers, performs
// 4 exact pairings in two stages — (rp0,q0),(rp1,q1) then (rp0,q1),(rp1,q0) —
// and writes each smem column back once, only if touched. 16 rounds cover
// all 32x32 reg-x-smem pairs with HALF the LDS/STS traffic of 32 rounds.
// Clean-pair matrix skips fully-converged block pairs.
__global__ void __launch_bounds__(512, 2) k_jacobi() {
    int c = blockIdx.x;
    float* Bg = g_B + (size_t)c * HW;
    int t = threadIdx.x, lane = t & 31, w = t >> 5;   // w in 0..15

    __shared__ float sj[8192];     // 32KB: one 32-column block
    __shared__ float snj[32];      // column norms^2 of smem block
    __shared__ int s_flag;         // any rotation this sweep
    __shared__ int s_dirty;        // any rotation this phase
    __shared__ int s_any;          // any rotation this bi iteration
    __shared__ int s_skip;         // whole bi iteration clean
    __shared__ unsigned char s_clean[8][8];

    if (t < 64) s_clean[t >> 3][t & 7] = 0;
    __syncthreads();

    for (int sweep = 0; sweep < NSWMAX; sweep++) {
        if (t == 0) s_flag = 0;
        __syncthreads();
        for (int bi = 0; bi < 8; bi++) {
            // ---- whole-iteration skip check
            if (t == 0) {
                int ac = s_clean[bi][bi];
                for (int bj = bi + 1; bj < 8; bj++) ac &= s_clean[bi][bj];
                s_skip = ac;
            }
            __syncthreads();
            if (s_skip) continue;   // uniform

            // ---- load block bi: warp w loads cols w, w+16 + computes norms
#pragma unroll
            for (int h = 0; h < 2; h++) {
                int col = w + 16 * h;
                const float4* src = (const float4*)(Bg + (bi * 32 + col) * 256);
                float4* dst = (float4*)(sj + col * 256);
                float4 v0 = src[lane * 2], v1 = src[lane * 2 + 1];
                dst[lane * 2] = v0; dst[lane * 2 + 1] = v1;
                float a = v0.x*v0.x + v0.y*v0.y + v0.z*v0.z + v0.w*v0.w
                        + v1.x*v1.x + v1.y*v1.y + v1.z*v1.z + v1.w*v1.w;
                a = warp_sum(a);
                if (lane == 0) snj[col] = a;
            }
            if (t == 0) { s_any = 0; s_dirty = 0; }
            __syncthreads();

            // ---- intra-block tournament (only if not converged)
            int do_intra = (s_clean[bi][bi] == 0);   // uniform, stable
            if (do_intra) {
                for (int r = 0; r < 31; r++) {
                    int p = (w == 0) ? 0 : 1 + (w - 1 + r) % 31;
                    int q = 1 + (30 - w + r) % 31;
                    float4* cp = (float4*)(sj + p * 256);
                    float4* cq = (float4*)(sj + q * 256);
                    float4 p0 = cp[lane * 2], p1 = cp[lane * 2 + 1];
                    float4 q0 = cq[lane * 2], q1 = cq[lane * 2 + 1];
                    float apq = p0.x * q0.x;
                    apq = fmaf(p0.y, q0.y, apq);
                    apq = fmaf(p0.z, q0.z, apq);
                    apq = fmaf(p0.w, q0.w, apq);
                    apq = fmaf(p1.x, q1.x, apq);
                    apq = fmaf(p1.y, q1.y, apq);
                    apq = fmaf(p1.z, q1.z, apq);
                    apq = fmaf(p1.w, q1.w, apq);
                    apq = warp_sum(apq);
                    float app = snj[p], aqq = snj[q];
                    if (apq * apq > ROTTHR * app * aqq) {
                        float tau = (aqq - app) / (2.0f * apq);
                        float tt  = copysignf(1.0f, tau) / (fabsf(tau) + sqrtf(1.0f + tau * tau));
                        float cth = 1.0f / sqrtf(1.0f + tt * tt);
                        float sth = tt * cth;
                        float4 np, nq;
                        np.x = cth*p0.x - sth*q0.x;  nq.x = sth*p0.x + cth*q0.x;
                        np.y = cth*p0.y - sth*q0.y;  nq.y = sth*p0.y + cth*q0.y;
                        np.z = cth*p0.z - sth*q0.z;  nq.z = sth*p0.z + cth*q0.z;
                        np.w = cth*p0.w - sth*q0.w;  nq.w = sth*p0.w + cth*q0.w;
                        cp[lane * 2] = np;  cq[lane * 2] = nq;
                        np.x = cth*p1.x - sth*q1.x;  nq.x = sth*p1.x + cth*q1.x;
                        np.y = cth*p1.y - sth*q1.y;  nq.y = sth*p1.y + cth*q1.y;
                        np.z = cth*p1.z - sth*q1.z;  nq.z = sth*p1.z + cth*q1.z;
                        np.w = cth*p1.w - sth*q1.w;  nq.w = sth*p1.w + cth*q1.w;
                        cp[lane * 2 + 1] = np;  cq[lane * 2 + 1] = nq;
                        if (lane == 0) {
                            snj[p] = app - tt * apq;
                            snj[q] = aqq + tt * apq;
                            s_flag = 1; s_any = 1; s_dirty = 1;
                        }
                    }
                    __syncthreads();
                }
                // clean-matrix update from intra result (s_dirty stable: post-barrier)
                if (t == 0) {
                    if (s_dirty) {
                        for (int k2 = 0; k2 < 8; k2++) { s_clean[bi][k2] = 0; s_clean[k2][bi] = 0; }
                    } else {
                        s_clean[bi][bi] = 1;
                    }
                }
                // settled by the barrier at top of bj loop below
            }

            // ---- move cols w and w+16 of bi into registers (exact norms)
            float rp0[8], rp1[8], app0, app1;
            {
                const float4* c0 = (const float4*)(sj + w * 256);
                float4 a0 = c0[lane * 2], a1 = c0[lane * 2 + 1];
                rp0[0]=a0.x; rp0[1]=a0.y; rp0[2]=a0.z; rp0[3]=a0.w;
                rp0[4]=a1.x; rp0[5]=a1.y; rp0[6]=a1.z; rp0[7]=a1.w;
                float a = 0.f;
#pragma unroll
                for (int m = 0; m < 8; m++) a = fmaf(rp0[m], rp0[m], a);
                app0 = warp_sum(a);
                const float4* c1 = (const float4*)(sj + (w + 16) * 256);
                float4 b0 = c1[lane * 2], b1 = c1[lane * 2 + 1];
                rp1[0]=b0.x; rp1[1]=b0.y; rp1[2]=b0.z; rp1[3]=b0.w;
                rp1[4]=b1.x; rp1[5]=b1.y; rp1[6]=b1.z; rp1[7]=b1.w;
                float b = 0.f;
#pragma unroll
                for (int m = 0; m < 8; m++) b = fmaf(rp1[m], rp1[m], b);
                app1 = warp_sum(b);
            }

            // ---- cross-block phases
            for (int bj = bi + 1; bj < 8; bj++) {
                __syncthreads();   // settle clean-matrix writes from prior phase/intra
                int do_cross = (s_clean[bi][bj] == 0);   // uniform
                if (!do_cross) continue;

                // load bj (own cols — same-warp ordering vs. prior reads)
#pragma unroll
                for (int h = 0; h < 2; h++) {
                    int col = w + 16 * h;
                    const float4* src = (const float4*)(Bg + (bj * 32 + col) * 256);
                    float4* dst = (float4*)(sj + col * 256);
                    float4 v0 = src[lane * 2], v1 = src[lane * 2 + 1];
                    dst[lane * 2] = v0; dst[lane * 2 + 1] = v1;
                    float a = v0.x*v0.x + v0.y*v0.y + v0.z*v0.z + v0.w*v0.w
                            + v1.x*v1.x + v1.y*v1.y + v1.z*v1.z + v1.w*v1.w;
                    a = warp_sum(a);
                    if (lane == 0) snj[col] = a;
                }
                if (t == 0) s_dirty = 0;
                __syncthreads();

                // 16 rounds; warp claims smem col pair (2*qp, 2*qp+1)
                for (int r = 0; r < 16; r++) {
                    int qp = (w + r) & 15;
                    int q0i = 2 * qp, q1i = 2 * qp + 1;
                    float4* cq0 = (float4*)(sj + q0i * 256);
                    float4* cq1 = (float4*)(sj + q1i * 256);
                    float4 x0 = cq0[lane * 2], x1 = cq0[lane * 2 + 1];
                    float4 y0 = cq1[lane * 2], y1 = cq1[lane * 2 + 1];
                    float bq0[8] = {x0.x,x0.y,x0.z,x0.w,x1.x,x1.y,x1.z,x1.w};
                    float bq1[8] = {y0.x,y0.y,y0.z,y0.w,y1.x,y1.y,y1.z,y1.w};
                    float aqq0 = snj[q0i], aqq1 = snj[q1i];
                    bool wr0 = false, wr1 = false, hit = false;

                    // stage 1: (rp0,bq0) and (rp1,bq1) — disjoint, exact dots
                    {
                        float d0 = 0.f, d1 = 0.f;
#pragma unroll
                        for (int m = 0; m < 8; m++) {
                            d0 = fmaf(rp0[m], bq0[m], d0);
                            d1 = fmaf(rp1[m], bq1[m], d1);
                        }
#pragma unroll
                        for (int o = 16; o > 0; o >>= 1) {
                            d0 += __shfl_xor_sync(0xFFFFFFFFu, d0, o);
                            d1 += __shfl_xor_sync(0xFFFFFFFFu, d1, o);
                        }
                        if (d0 * d0 > ROTTHR * app0 * aqq0) {
                            ROT_APPLY(rp0, bq0, app0, aqq0, d0);
                            wr0 = true; hit = true;
                        }
                        if (d1 * d1 > ROTTHR * app1 * aqq1) {
                            ROT_APPLY(rp1, bq1, app1, aqq1, d1);
                            wr1 = true; hit = true;
                        }
                    }
                    // stage 2: (rp0,bq1) and (rp1,bq0) — disjoint, exact dots
                    {
                        float d2 = 0.f, d3 = 0.f;
#pragma unroll
                        for (int m = 0; m < 8; m++) {
                            d2 = fmaf(rp0[m], bq1[m], d2);
                            d3 = fmaf(rp1[m], bq0[m], d3);
                        }
#pragma unroll
                        for (int o = 16; o > 0; o >>= 1) {
                            d2 += __shfl_xor_sync(0xFFFFFFFFu, d2, o);
                            d3 += __shfl_xor_sync(0xFFFFFFFFu, d3, o);
                        }
                        if (d2 * d2 > ROTTHR * app0 * aqq1) {
                            ROT_APPLY(rp0, bq1, app0, aqq1, d2);
                            wr1 = true; hit = true;
                        }
                        if (d3 * d3 > ROTTHR * app1 * aqq0) {
                            ROT_APPLY(rp1, bq0, app1, aqq0, d3);
                            wr0 = true; hit = true;
                        }
                    }
                    // write back touched smem columns once
                    if (wr0) {
                        cq0[lane * 2]     = make_float4(bq0[0], bq0[1], bq0[2], bq0[3]);
                        cq0[lane * 2 + 1] = make_float4(bq0[4], bq0[5], bq0[6], bq0[7]);
                    }
                    if (wr1) {
                        cq1[lane * 2]     = make_float4(bq1[0], bq1[1], bq1[2], bq1[3]);
                        cq1[lane * 2 + 1] = make_float4(bq1[4], bq1[5], bq1[6], bq1[7]);
                    }
                    if (lane == 0) {
                        snj[q0i] = aqq0; snj[q1i] = aqq1;
                        if (hit) { s_flag = 1; s_dirty = 1; s_any = 1; }
                    }
                    __syncthreads();
                }
                // store bj back + clean bookkeeping (s_dirty stable post-barrier)
                if (s_dirty) {
#pragma unroll
                    for (int h = 0; h < 2; h++) {
                        int col = w + 16 * h;
                        float4* dst = (float4*)(Bg + (bj * 32 + col) * 256);
                        const float4* src = (const float4*)(sj + col * 256);
                        dst[lane * 2] = src[lane * 2];
                        dst[lane * 2 + 1] = src[lane * 2 + 1];
                    }
                    if (t == 0) {
                        for (int k2 = 0; k2 < 8; k2++) {
                            s_clean[bi][k2] = 0; s_clean[k2][bi] = 0;
                            s_clean[bj][k2] = 0; s_clean[k2][bj] = 0;
                        }
                    }
                } else {
                    if (t == 0) { s_clean[bi][bj] = 1; s_clean[bj][bi] = 1; }
                }
                // settled by barrier at top of next bj iteration (or bi-end barrier)
            }
            __syncthreads();   // settle last phase's clean writes + sj reads
            // ---- store register columns back only if bi iteration rotated at all
            if (s_any) {
                ((float4*)(Bg + (bi * 32 + w) * 256))[lane * 2] =
                    make_float4(rp0[0], rp0[1], rp0[2], rp0[3]);
                ((float4*)(Bg + (bi * 32 + w) * 256))[lane * 2 + 1] =
                    make_float4(rp0[4], rp0[5], rp0[6], rp0[7]);
                ((float4*)(Bg + (bi * 32 + w + 16) * 256))[lane * 2] =
                    make_float4(rp1[0], rp1[1], rp1[2], rp1[3]);
                ((float4*)(Bg + (bi * 32 + w + 16) * 256))[lane * 2 + 1] =
                    make_float4(rp1[4], rp1[5], rp1[6], rp1[7]);
            }
            __syncthreads();
        }
        __syncthreads();
        int done = (s_flag == 0);
        __syncthreads();
        if (done) break;
    }
}

// ---------------- stage 4: column norms, rank, keep factor ----------------
__global__ void k_fact() {
    int c = blockIdx.x, t = threadIdx.x, lane = t & 31, w = t >> 5;
    __shared__ float s2[256];
    const float* B = g_B + (size_t)c * HW;
    for (int j = w; j < 256; j += 8) {
        const float* col = B + j * 256;
        float a = 0.f;
#pragma unroll
        for (int m = 0; m < 8; m++) {
            float v = col[lane + 32 * m];
            a = fmaf(v, v, a);
        }
        a = warp_sum(a);
        if (lane == 0) s2[j] = a;
    }
    __syncthreads();
    float mys = s2[t];
    int kc = g_k[c];
    int rank = 0;
    for (int j = 0; j < 256; j++) {
        float v = s2[j];
        rank += (v > mys) || (v == mys && j < t);
    }
    g_fact[c * 256 + t] = (rank < kc) ? 1.0f / fmaxf(mys, 1e-20f) : 0.0f;
}

// ---------------- stage 5: T = diag(f) * B^T A  (C = M*N, M row-major = B^T) ----------
__global__ void __launch_bounds__(256) k_gemmT(const float* __restrict__ x) {
    int c = blockIdx.z;
    const float* M = g_B + (size_t)c * HW;   // M[j][i] = B(i,j)
    const float* N = x + (size_t)c * HW;     // A row-major
    float* C = g_T + (size_t)c * HW;
    int m0 = blockIdx.y * 64, n0 = blockIdx.x * 64;
    __shared__ float Ms[16][68], Ns[16][68];
    int t = threadIdx.x;
    int tx = t & 15, ty = t >> 4;
    float acc[4][4] = {};
    for (int k0 = 0; k0 < 256; k0 += 16) {
#pragma unroll
        for (int u = 0; u < 4; u++) {
            int id = t + 256 * u;
            int kk = id & 15, mm = id >> 4;
            Ms[kk][mm] = M[(m0 + mm) * 256 + k0 + kk];
        }
#pragma unroll
        for (int u = 0; u < 4; u++) {
            int id = t + 256 * u;
            int kk = id >> 6, nn = id & 63;
            Ns[kk][nn] = N[(k0 + kk) * 256 + n0 + nn];
        }
        __syncthreads();
#pragma unroll
        for (int kk = 0; kk < 16; kk++) {
            float a[4], b[4];
#pragma unroll
            for (int i = 0; i < 4; i++) a[i] = Ms[kk][ty * 4 + i];
#pragma unroll
            for (int j = 0; j < 4; j++) b[j] = Ns[kk][tx * 4 + j];
#pragma unroll
            for (int i = 0; i < 4; i++)
#pragma unroll
                for (int j = 0; j < 4; j++) acc[i][j] = fmaf(a[i], b[j], acc[i][j]);
        }
        __syncthreads();
    }
    const float* f = g_fact + c * 256;
#pragma unroll
    for (int i = 0; i < 4; i++) {
        float fi = f[m0 + ty * 4 + i];
#pragma unroll
        for (int j = 0; j < 4; j++)
            C[(m0 + ty * 4 + i) * 256 + n0 + tx * 4 + j] = acc[i][j] * fi;
    }
}

// ---------------- stage 6: R = B * T  (= M^T * N with M as above) ----------------
__global__ void __launch_bounds__(256) k_gemmR() {
    int c = blockIdx.z;
    const float* M = g_B + (size_t)c * HW;   // M[j][i] = B(i,j); need M^T * T
    const float* N = g_T + (size_t)c * HW;
    float* C = g_R + (size_t)c * HW;
    int m0 = blockIdx.y * 64, n0 = blockIdx.x * 64;
    __shared__ float Ms[16][68], Ns[16][68];
    int t = threadIdx.x;
    int tx = t & 15, ty = t >> 4;
    float acc[4][4] = {};
    for (int k0 = 0; k0 < 256; k0 += 16) {
#pragma unroll
        for (int u = 0; u < 4; u++) {
            int id = t + 256 * u;
            int kk = id >> 6, mm = id & 63;
            Ms[kk][mm] = M[(k0 + kk) * 256 + m0 + mm];   // M^T tile, coalesced
        }
#pragma unroll
        for (int u = 0; u < 4; u++) {
            int id = t + 256 * u;
            int kk = id >> 6, nn = id & 63;
            Ns[kk][nn] = N[(k0 + kk) * 256 + n0 + nn];
        }
        __syncthreads();
#pragma unroll
        for (int kk = 0; kk < 16; kk++) {
            float a[4], b[4];
#pragma unroll
            for (int i = 0; i < 4; i++) a[i] = Ms[kk][ty * 4 + i];
#pragma unroll
            for (int j = 0; j < 4; j++) b[j] = Ns[kk][tx * 4 + j];
#pragma unroll
            for (int i = 0; i < 4; i++)
#pragma unroll
                for (int j = 0; j < 4; j++) acc[i][j] = fmaf(a[i], b[j], acc[i][j]);
        }
        __syncthreads();
    }
#pragma unroll
    for (int i = 0; i < 4; i++)
#pragma unroll
        for (int j = 0; j < 4; j++)
            C[(m0 + ty * 4 + i) * 256 + n0 + tx * 4 + j] = acc[i][j];
}

// ---------------- stage 7: channel mean & max of recon ----------------
__global__ void k_avgmax() {
    int pix = blockIdx.x * 1024 + threadIdx.x;
    float s = 0.f, m = -3.4e38f;
    for (int c = 0; c < 256; c++) {
        float v = g_R[(size_t)c * HW + pix];
        s += v;
        m = fmaxf(m, v);
    }
    g_cat[pix]      = s * (1.0f / 256.0f);
    g_cat[HW + pix] = m;
}

// ---------------- stage 8: 7x7 conv (pad 3) + EPS clamp + sigmoid ----------------
__global__ void k_conv(const float* __restrict__ cw, float* __restrict__ out) {
    __shared__ float wsm[98];
    int tx = threadIdx.x, ty = threadIdx.y;
    int tid = ty * 32 + tx;
    if (tid < 98) wsm[tid] = cw[tid];
    __syncthreads();
    int gx = blockIdx.x * 32 + tx;
    int gy = blockIdx.y * 8 + ty;
    float acc = 0.f;
#pragma unroll
    for (int ci = 0; ci < 2; ci++) {
#pragma unroll
        for (int kh = 0; kh < 7; kh++) {
            int iy = gy + kh - 3;
            if (iy < 0 || iy > 255) continue;
#pragma unroll
            for (int kw = 0; kw < 7; kw++) {
                int ix = gx + kw - 3;
                if (ix < 0 || ix > 255) continue;
                acc = fmaf(g_cat[ci * HW + iy * 256 + ix], wsm[ci * 49 + kh * 7 + kw], acc);
            }
        }
    }
    const float EPSF = 2.220446049250313e-16f;
    if (acc < EPSF) acc = EPSF;
    out[gy * 256 + gx] = 1.0f / (1.0f + expf(-acc));
}

// ---------------- launch ----------------
extern "C" void kernel_launch(void* const* d_in, const int* in_sizes, int n_in,
                              void* d_out, int out_size) {
    const float* x  = (const float*)d_in[0];
    const float* w1 = (const float*)d_in[1];
    const float* w2 = (const float*)d_in[2];
    const float* cw = (const float*)d_in[3];
    const int*   kv = (const int*)d_in[4];

    k_stats<<<256, 256>>>(x);
    k_att<<<1, 256>>>(w1, w2, kv);
    k_tr<<<dim3(8, 8, 256), dim3(32, 8)>>>(x);
    k_jacobi<<<256, 512>>>();
    k_fact<<<256, 256>>>();
    k_gemmT<<<dim3(4, 4, 256), 256>>>(x);
    k_gemmR<<<dim3(4, 4, 256), 256>>>();
    k_avgmax<<<64, 1024>>>();
    k_conv<<<dim3(8, 32), dim3(32, 8)>>>(cw, (float*)d_out);
}